// round 5
// baseline (speedup 1.0000x reference)
#include <cuda_runtime.h>
#include <cuda_bf16.h>
#include <cstdint>
#include <cstddef>

// ---------------------------------------------------------------------------
// Problem constants
// ---------------------------------------------------------------------------
#define B_   128
#define S_   256
#define H_   1024
#define IN_  64
#define SD_  2
#define KTOT 1090
#define NKB  36              // K blocks of 32 (KPAD = 1152)
#define ZW   (SD_ + H_)      // 1026
#define NG   4096

#define OUT_ZF   ((size_t)B_ * S_ * ZW)
#define OUT_CZF  (OUT_ZF + (size_t)B_ * ZW)
#define OUT_COEF (OUT_CZF + (size_t)B_ * ZW)

// Blocked layouts: rows padded to 40 bf16 (80 B) for conflict-free LDS
#define ROWB 40
#define XBLK_BYTES  (128 * ROWB * 2)          // 10240 per K-block
#define WBLK_BYTES  (32 * ROWB * 2)           // 2560 per (ntile, kb)
#define STAGE_BYTES (2 * XBLK_BYTES + 2 * WBLK_BYTES)   // 25600
#define SMEM_DYN    (128 + 2 * STAGE_BYTES)             // 51328

// ---------------------------------------------------------------------------
// Device-global scratch (double-buffered X images)
// ---------------------------------------------------------------------------
__device__ __align__(128) __nv_bfloat16 g_Xhi[2][(size_t)NKB * 128 * ROWB];
__device__ __align__(128) __nv_bfloat16 g_Xlo[2][(size_t)NKB * 128 * ROWB];
__device__ __align__(128) __nv_bfloat16 g_Whi[(size_t)128 * NKB * 32 * ROWB];
__device__ __align__(128) __nv_bfloat16 g_Wlo[(size_t)128 * NKB * 32 * ROWB];
__device__ float g_part2[(size_t)B_ * 128 * 4];   // [b][ntile][4] Wa/Wx partials
__device__ float g_cstate[B_ * H_];
__device__ float g_xstate[B_ * 2];

// ---------------------------------------------------------------------------
// Helpers
// ---------------------------------------------------------------------------
__device__ __forceinline__ float sigf(float x) { return 1.0f / (1.0f + __expf(-x)); }
__device__ __forceinline__ float tanhfast(float x) { return 2.0f / (1.0f + __expf(-2.0f * x)) - 1.0f; }

__device__ __forceinline__ void store_x_hilo(int img, int m, int k, float v) {
    int kb = k >> 5, kk = k & 31;
    size_t idx = ((size_t)kb * 128 + m) * ROWB + kk;
    __nv_bfloat16 hi = __float2bfloat16_rn(v);
    float r = v - __bfloat162float(hi);
    g_Xhi[img][idx] = hi;
    g_Xlo[img][idx] = __float2bfloat16_rn(r);
}

__device__ __forceinline__ uint32_t smem_u32(const void* p) {
    uint32_t a;
    asm("{ .reg .u64 t; cvta.to.shared.u64 t, %1; cvt.u32.u64 %0, t; }" : "=r"(a) : "l"(p));
    return a;
}

#define MBINIT(a, c)  asm volatile("mbarrier.init.shared.b64 [%0], %1;" :: "r"(a), "r"(c) : "memory")
#define MBEXPECT(a,b) asm volatile("mbarrier.arrive.expect_tx.shared.b64 _, [%0], %1;" :: "r"(a), "r"(b) : "memory")
#define MBARRIVE(a)   asm volatile("mbarrier.arrive.shared.b64 _, [%0];" :: "r"(a) : "memory")

#define MBAR_WAIT(mbar, ph) do {                                             \
    uint32_t _m = (mbar); uint32_t _p = (ph); uint32_t _ok;                  \
    asm volatile("{\n\t.reg .pred p;\n\t"                                    \
        "mbarrier.try_wait.parity.acquire.cta.shared::cta.b64 p, [%1], %2;\n\t" \
        "selp.b32 %0, 1, 0, p;\n\t}" : "=r"(_ok) : "r"(_m), "r"(_p) : "memory"); \
    while (!_ok) {                                                           \
        asm volatile("{\n\t.reg .pred p;\n\t"                                \
            "mbarrier.try_wait.parity.acquire.cta.shared::cta.b64 p, [%1], %2, 0x989680;\n\t" \
            "selp.b32 %0, 1, 0, p;\n\t}" : "=r"(_ok) : "r"(_m), "r"(_p) : "memory"); \
    }                                                                        \
} while (0)

__device__ __forceinline__ void bulk_g2s(uint32_t dst, const void* src, uint32_t bytes, uint32_t mbar) {
    asm volatile("cp.async.bulk.shared::cluster.global.mbarrier::complete_tx::bytes [%0], [%1], %2, [%3];"
                 :: "r"(dst), "l"(src), "r"(bytes), "r"(mbar) : "memory");
}

#define MMA_BF16(acc, a, b)                                                  \
    asm volatile("mma.sync.aligned.m16n8k16.row.col.f32.bf16.bf16.f32 "      \
                 "{%0,%1,%2,%3},{%4,%5,%6,%7},{%8,%9},{%0,%1,%2,%3};"        \
                 : "+f"((acc)[0]), "+f"((acc)[1]), "+f"((acc)[2]), "+f"((acc)[3]) \
                 : "r"((a)[0]), "r"((a)[1]), "r"((a)[2]), "r"((a)[3]),       \
                   "r"((b)[0]), "r"((b)[1]))

// Unit-major permutation: global col n -> W row (n&3)*H + (n>>5)*8 + ((n&31)>>2)
__device__ __forceinline__ int orig_row(int nt, int j) {
    return (j & 3) * H_ + nt * 8 + (j >> 2);
}

// ---------------------------------------------------------------------------
// prep_w: W [4096][1090] fp32 -> blocked, unit-major-permuted split-bf16 images
// grid (128 ntiles, 36 kb), 128 threads
// ---------------------------------------------------------------------------
__global__ void prep_w(const float* __restrict__ W) {
    int nt = blockIdx.x, kb = blockIdx.y;
    size_t base = ((size_t)(nt * NKB + kb)) * 32 * ROWB;
    for (int i = threadIdx.x; i < 32 * ROWB; i += 128) {
        int nloc = i / ROWB, kk = i % ROWB;
        int n = orig_row(nt, nloc);
        int k = kb * 32 + kk;
        float v = (kk < 32 && k < KTOT) ? W[(size_t)n * KTOT + k] : 0.0f;
        __nv_bfloat16 hi = __float2bfloat16_rn(v);
        float r = v - __bfloat162float(hi);
        g_Whi[base + i] = hi;
        g_Wlo[base + i] = __float2bfloat16_rn(r);
    }
}

// ---------------------------------------------------------------------------
// init_pack: X image 0 for step 0 (incl. pads), states
// ---------------------------------------------------------------------------
__global__ void init_pack(const float* __restrict__ z0, const float* __restrict__ c0,
                          const float* __restrict__ rnn_input) {
    int b = blockIdx.x;
    for (int i = threadIdx.x; i < NKB * ROWB; i += 128) {
        int kb = i / ROWB, kk = i % ROWB;
        int k = kb * 32 + kk;
        float v = 0.0f;
        if (kk < 32) {
            if (k < SD_)            v = z0[b * ZW + k];
            else if (k < SD_ + IN_) v = rnn_input[((size_t)b * S_) * IN_ + (k - SD_)];
            else if (k < KTOT)      v = z0[b * ZW + SD_ + (k - (SD_ + IN_))];
        }
        size_t idx = ((size_t)kb * 128 + b) * ROWB + kk;
        __nv_bfloat16 hi = __float2bfloat16_rn(v);
        float r = v - __bfloat162float(hi);
        g_Xhi[0][idx] = hi;
        g_Xlo[0][idx] = __float2bfloat16_rn(r);
        // zero the pad region of image 1 as well (h/x/u regions get overwritten)
        g_Xhi[1][idx] = hi;
        g_Xlo[1][idx] = __float2bfloat16_rn(r);
    }
    for (int n = threadIdx.x; n < H_; n += 128)
        g_cstate[b * H_ + n] = c0[b * ZW + SD_ + n];
    if (threadIdx.x < 2) g_xstate[b * 2 + threadIdx.x] = z0[b * ZW + threadIdx.x];
}

// ---------------------------------------------------------------------------
// gates_fused: split-bf16 HMMA GEMM + fused LSTM pointwise epilogue
// grid = 128 CTAs (8 hidden units each, unit-major cols), 128 threads
// ---------------------------------------------------------------------------
__global__ void __launch_bounds__(128, 1)
gates_fused(int s, float* __restrict__ out,
            const float* __restrict__ WUb,
            const float* __restrict__ Wa, const float* __restrict__ Wx) {
    extern __shared__ char dsm[];
    uint32_t ub = smem_u32(dsm);
    const int nt  = blockIdx.x;
    const int tid = threadIdx.x;
    const int wid = tid >> 5;
    const int lane = tid & 31;
    const int lr = lane >> 2, lc = lane & 3;
    const int wm = wid * 32;
    const int img_r = s & 1, img_w = (s + 1) & 1;

    __shared__ float sb_bias[32];
    __shared__ float sWa0[8], sWa1[8], sWx0[8], sWx1[8];

    uint32_t mb_full[2]  = {ub + 0,  ub + 8};
    uint32_t mb_empty[2] = {ub + 16, ub + 24};
    char* tiles = dsm + 128;

    if (tid < 32) sb_bias[tid] = WUb[orig_row(nt, tid)];
    if (tid >= 32 && tid < 40) {
        int u = nt * 8 + (tid - 32);
        sWa0[tid - 32] = Wa[u];       sWa1[tid - 32] = Wa[H_ + u];
        sWx0[tid - 32] = Wx[u];       sWx1[tid - 32] = Wx[H_ + u];
    }
    if (tid == 0) {
        MBINIT(mb_full[0], 1);  MBINIT(mb_full[1], 1);
        MBINIT(mb_empty[0], 128); MBINIT(mb_empty[1], 128);
        asm volatile("fence.proxy.async.shared::cta;" ::: "memory");
    }
    __syncthreads();

    const __nv_bfloat16* Xhi = g_Xhi[img_r];
    const __nv_bfloat16* Xlo = g_Xlo[img_r];

    if (tid == 0) {
#pragma unroll
        for (int kb = 0; kb < 2; kb++) {
            int st = kb;
            uint32_t sb = ub + 128 + st * STAGE_BYTES;
            MBEXPECT(mb_full[st], STAGE_BYTES);
            bulk_g2s(sb,              (const char*)Xhi + (size_t)kb * XBLK_BYTES, XBLK_BYTES, mb_full[st]);
            bulk_g2s(sb + XBLK_BYTES, (const char*)Xlo + (size_t)kb * XBLK_BYTES, XBLK_BYTES, mb_full[st]);
            size_t woff = (size_t)(nt * NKB + kb) * WBLK_BYTES;
            bulk_g2s(sb + 2 * XBLK_BYTES,              (const char*)g_Whi + woff, WBLK_BYTES, mb_full[st]);
            bulk_g2s(sb + 2 * XBLK_BYTES + WBLK_BYTES, (const char*)g_Wlo + woff, WBLK_BYTES, mb_full[st]);
        }
    }

    float acc[2][4][4];
#pragma unroll
    for (int mi = 0; mi < 2; mi++)
#pragma unroll
        for (int ni = 0; ni < 4; ni++)
#pragma unroll
            for (int e = 0; e < 4; e++) acc[mi][ni][e] = 0.0f;

    int fph[2] = {0, 0}, eph[2] = {0, 0};

    for (int kb = 0; kb < NKB; kb++) {
        int st = kb & 1;
        char* sx_hi = tiles + st * STAGE_BYTES;
        char* sx_lo = sx_hi + XBLK_BYTES;
        char* sw_hi = sx_hi + 2 * XBLK_BYTES;
        char* sw_lo = sw_hi + WBLK_BYTES;

        MBAR_WAIT(mb_full[st], fph[st]); fph[st] ^= 1;

#pragma unroll
        for (int ks = 0; ks < 2; ks++) {
            uint32_t ahi[2][4], alo[2][4], bhi[4][2], blo[4][2];
#pragma unroll
            for (int mi = 0; mi < 2; mi++) {
                int o = (wm + mi * 16 + lr) * 80 + ks * 32 + lc * 4;
                ahi[mi][0] = *(const uint32_t*)(sx_hi + o);
                ahi[mi][1] = *(const uint32_t*)(sx_hi + o + 640);
                ahi[mi][2] = *(const uint32_t*)(sx_hi + o + 16);
                ahi[mi][3] = *(const uint32_t*)(sx_hi + o + 656);
                alo[mi][0] = *(const uint32_t*)(sx_lo + o);
                alo[mi][1] = *(const uint32_t*)(sx_lo + o + 640);
                alo[mi][2] = *(const uint32_t*)(sx_lo + o + 16);
                alo[mi][3] = *(const uint32_t*)(sx_lo + o + 656);
            }
#pragma unroll
            for (int ni = 0; ni < 4; ni++) {
                int o = (ni * 8 + lr) * 80 + ks * 32 + lc * 4;
                bhi[ni][0] = *(const uint32_t*)(sw_hi + o);
                bhi[ni][1] = *(const uint32_t*)(sw_hi + o + 16);
                blo[ni][0] = *(const uint32_t*)(sw_lo + o);
                blo[ni][1] = *(const uint32_t*)(sw_lo + o + 16);
            }
#pragma unroll
            for (int mi = 0; mi < 2; mi++)
#pragma unroll
                for (int ni = 0; ni < 4; ni++) {
                    MMA_BF16(acc[mi][ni], ahi[mi], bhi[ni]);
                    MMA_BF16(acc[mi][ni], ahi[mi], blo[ni]);
                    MMA_BF16(acc[mi][ni], alo[mi], bhi[ni]);
                }
        }

        MBARRIVE(mb_empty[st]);

        if (tid == 0 && kb + 2 < NKB) {
            MBAR_WAIT(mb_empty[st], eph[st]); eph[st] ^= 1;
            int kn = kb + 2;
            uint32_t sb = ub + 128 + st * STAGE_BYTES;
            MBEXPECT(mb_full[st], STAGE_BYTES);
            bulk_g2s(sb,              (const char*)Xhi + (size_t)kn * XBLK_BYTES, XBLK_BYTES, mb_full[st]);
            bulk_g2s(sb + XBLK_BYTES, (const char*)Xlo + (size_t)kn * XBLK_BYTES, XBLK_BYTES, mb_full[st]);
            size_t woff = (size_t)(nt * NKB + kn) * WBLK_BYTES;
            bulk_g2s(sb + 2 * XBLK_BYTES,              (const char*)g_Whi + woff, WBLK_BYTES, mb_full[st]);
            bulk_g2s(sb + 2 * XBLK_BYTES + WBLK_BYTES, (const char*)g_Wlo + woff, WBLK_BYTES, mb_full[st]);
        }
    }

    // ---- Fused epilogue: stage accs in smem (alias tile region), LSTM math ----
    __syncthreads();
    float* sg = (float*)(dsm + 128);   // [128][33]
#pragma unroll
    for (int mi = 0; mi < 2; mi++) {
        int b0 = wm + mi * 16 + lr;
#pragma unroll
        for (int ni = 0; ni < 4; ni++) {
            int j = ni * 8 + lc * 2;
            sg[b0 * 33 + j]           = acc[mi][ni][0];
            sg[b0 * 33 + j + 1]       = acc[mi][ni][1];
            sg[(b0 + 8) * 33 + j]     = acc[mi][ni][2];
            sg[(b0 + 8) * 33 + j + 1] = acc[mi][ni][3];
        }
    }
    __syncthreads();

    const int b = tid;
    float wa0 = 0.f, wa1 = 0.f, wx0 = 0.f, wx1 = 0.f;
    float* outz = out + ((size_t)b * S_ + s) * ZW + SD_;
#pragma unroll
    for (int uu = 0; uu < 8; uu++) {
        int ug = nt * 8 + uu;
        float iv = sg[b * 33 + 4 * uu + 0] + sb_bias[4 * uu + 0];
        float fv = sg[b * 33 + 4 * uu + 1] + sb_bias[4 * uu + 1];
        float gv = sg[b * 33 + 4 * uu + 2] + sb_bias[4 * uu + 2];
        float ov = sg[b * 33 + 4 * uu + 3] + sb_bias[4 * uu + 3];
        float c  = g_cstate[b * H_ + ug];
        float cn = sigf(fv) * c + sigf(iv) * tanhfast(gv);
        float hn = sigf(ov) * tanhfast(cn);
        g_cstate[b * H_ + ug] = cn;
        outz[ug] = hn;
        store_x_hilo(img_w, b, SD_ + IN_ + ug, hn);
        wa0 += sWa0[uu] * hn;  wa1 += sWa1[uu] * hn;
        wx0 += sWx0[uu] * hn;  wx1 += sWx1[uu] * hn;
    }
    float4 p = make_float4(wa0, wa1, wx0, wx1);
    ((float4*)g_part2)[(size_t)b * 128 + nt] = p;
}

// ---------------------------------------------------------------------------
// x_update: reduce per-tile partials, 2-dim ODE/alpha path, stage u_{s+1}
// grid = B_, 128 threads
// ---------------------------------------------------------------------------
__global__ void __launch_bounds__(128)
x_update(int s, float* __restrict__ out,
         const float* __restrict__ Wab, const float* __restrict__ Wxb,
         const float* __restrict__ Amat, const float* __restrict__ tau,
         const float* __restrict__ rnn_input) {
    const int b = blockIdx.x;
    const int t = threadIdx.x;
    const int img_w = (s + 1) & 1;

    float4 p = ((const float4*)g_part2)[(size_t)b * 128 + t];
    float wa0 = p.x, wa1 = p.y, wx0 = p.z, wx1 = p.w;

    __shared__ float red[4][4];
    unsigned mask = 0xffffffffu;
#pragma unroll
    for (int off = 16; off > 0; off >>= 1) {
        wa0 += __shfl_down_sync(mask, wa0, off);
        wa1 += __shfl_down_sync(mask, wa1, off);
        wx0 += __shfl_down_sync(mask, wx0, off);
        wx1 += __shfl_down_sync(mask, wx1, off);
    }
    if ((t & 31) == 0) {
        red[t >> 5][0] = wa0; red[t >> 5][1] = wa1;
        red[t >> 5][2] = wx0; red[t >> 5][3] = wx1;
    }
    __syncthreads();

    if (t == 0) {
        float s0 = red[0][0] + red[1][0] + red[2][0] + red[3][0];
        float s1 = red[0][1] + red[1][1] + red[2][1] + red[3][1];
        float s2 = red[0][2] + red[1][2] + red[2][2] + red[3][2];
        float s3 = red[0][3] + red[1][3] + red[2][3] + red[3][3];
        float xp0 = g_xstate[b * 2 + 0];
        float xp1 = g_xstate[b * 2 + 1];
        float tv  = tau[b * S_ + s];
        float xm0 = xp0 + tv * (Amat[0] * xp0 + Amat[1] * xp1);
        float xm1 = xp1 + tv * (Amat[2] * xp0 + Amat[3] * xp1);
        float a0  = sigf(s0 + Wab[0]);
        float a1  = sigf(s1 + Wab[1]);
        float xt0 = s2 + Wxb[0];
        float xt1 = s3 + Wxb[1];
        float xn0 = a0 * xm0 + (1.0f - a0) * xt0;
        float xn1 = a1 * xm1 + (1.0f - a1) * xt1;
        g_xstate[b * 2 + 0] = xn0;
        g_xstate[b * 2 + 1] = xn1;
        store_x_hilo(img_w, b, 0, xn0);
        store_x_hilo(img_w, b, 1, xn1);
        float* oz = out + ((size_t)b * S_ + s) * ZW;
        oz[0] = xn0;
        oz[1] = xn1;
        float* cf = out + OUT_COEF + ((size_t)b * S_ + s) * SD_;
        cf[0] = a0;
        cf[1] = a1;
    }

    if (s + 1 < S_ && t < IN_) {
        store_x_hilo(img_w, b, SD_ + t,
                     rnn_input[((size_t)b * S_ + (s + 1)) * IN_ + t]);
    }
}

// ---------------------------------------------------------------------------
// Final: z_f = outputs[:, -1, :], c_z_f = [c0[:, :2], c_final]
// ---------------------------------------------------------------------------
__global__ void final_out(const float* __restrict__ c0, float* __restrict__ out) {
    int b = blockIdx.x;
    float* zf  = out + OUT_ZF  + (size_t)b * ZW;
    float* czf = out + OUT_CZF + (size_t)b * ZW;
    const float* last = out + ((size_t)b * S_ + (S_ - 1)) * ZW;
    for (int k = threadIdx.x; k < ZW; k += 256) {
        zf[k] = last[k];
        czf[k] = (k < SD_) ? c0[b * ZW + k] : g_cstate[b * H_ + (k - SD_)];
    }
}

// ---------------------------------------------------------------------------
extern "C" void kernel_launch(void* const* d_in, const int* in_sizes, int n_in,
                              void* d_out, int out_size) {
    const float* rnn_input = (const float*)d_in[0];
    const float* z0        = (const float*)d_in[1];
    const float* c0        = (const float*)d_in[2];
    const float* tau       = (const float*)d_in[3];
    const float* A         = (const float*)d_in[4];
    const float* WU_w      = (const float*)d_in[5];
    const float* WU_b      = (const float*)d_in[6];
    const float* Wa_w      = (const float*)d_in[7];
    const float* Wa_b      = (const float*)d_in[8];
    const float* Wx_w      = (const float*)d_in[9];
    const float* Wx_b      = (const float*)d_in[10];
    float* out = (float*)d_out;

    cudaFuncSetAttribute(gates_fused, cudaFuncAttributeMaxDynamicSharedMemorySize, SMEM_DYN);

    prep_w<<<dim3(128, NKB), 128>>>(WU_w);
    init_pack<<<B_, 128>>>(z0, c0, rnn_input);
    for (int s = 0; s < S_; s++) {
        gates_fused<<<128, 128, SMEM_DYN>>>(s, out, WU_b, Wa_w, Wx_w);
        x_update<<<B_, 128>>>(s, out, Wa_b, Wx_b, A, tau, rnn_input);
    }
    final_out<<<B_, 256>>>(c0, out);
}

// round 6
// speedup vs baseline: 1.3635x; 1.3635x over previous
#include <cuda_runtime.h>
#include <cuda_bf16.h>
#include <cstdint>
#include <cstddef>

// ---------------------------------------------------------------------------
// Problem constants
// ---------------------------------------------------------------------------
#define B_   128
#define S_   256
#define H_   1024
#define IN_  64
#define SD_  2
#define KTOT 1090
#define NKB  36              // K blocks of 32 (KPAD = 1152)
#define ZW   (SD_ + H_)      // 1026
#define NG   4096

#define OUT_ZF   ((size_t)B_ * S_ * ZW)
#define OUT_CZF  (OUT_ZF + (size_t)B_ * ZW)
#define OUT_COEF (OUT_CZF + (size_t)B_ * ZW)

// Blocked layouts: rows padded to 40 bf16 (80 B) for conflict-free LDS
#define ROWB 40
#define XBLK_BYTES  (128 * ROWB * 2)          // 10240 per K-block
#define WBLK_BYTES  (32 * ROWB * 2)           // 2560 per (ntile, kb)
#define STAGE_BYTES (2 * XBLK_BYTES + 2 * WBLK_BYTES)   // 25600
#define SMEM_DYN    (128 + 2 * STAGE_BYTES)             // 51328

// ---------------------------------------------------------------------------
// Device-global scratch
// ---------------------------------------------------------------------------
__device__ __align__(128) __nv_bfloat16 g_Xhi[(size_t)NKB * 128 * ROWB];
__device__ __align__(128) __nv_bfloat16 g_Xlo[(size_t)NKB * 128 * ROWB];
__device__ __align__(128) __nv_bfloat16 g_Whi[(size_t)128 * NKB * 32 * ROWB];
__device__ __align__(128) __nv_bfloat16 g_Wlo[(size_t)128 * NKB * 32 * ROWB];
__device__ float g_gates[(size_t)B_ * NG];
__device__ float g_cstate[B_ * H_];
__device__ float g_xstate[B_ * 2];

// ---------------------------------------------------------------------------
// Helpers
// ---------------------------------------------------------------------------
__device__ __forceinline__ float sigf(float x) { return 1.0f / (1.0f + __expf(-x)); }
__device__ __forceinline__ float tanhfast(float x) { return 2.0f / (1.0f + __expf(-2.0f * x)) - 1.0f; }

__device__ __forceinline__ void store_x_hilo(int m, int k, float v) {
    int kb = k >> 5, kk = k & 31;
    size_t idx = ((size_t)kb * 128 + m) * ROWB + kk;
    __nv_bfloat16 hi = __float2bfloat16_rn(v);
    float r = v - __bfloat162float(hi);
    g_Xhi[idx] = hi;
    g_Xlo[idx] = __float2bfloat16_rn(r);
}

__device__ __forceinline__ uint32_t smem_u32(const void* p) {
    uint32_t a;
    asm("{ .reg .u64 t; cvta.to.shared.u64 t, %1; cvt.u32.u64 %0, t; }" : "=r"(a) : "l"(p));
    return a;
}

#define MBINIT(a, c)  asm volatile("mbarrier.init.shared.b64 [%0], %1;" :: "r"(a), "r"(c) : "memory")
#define MBEXPECT(a,b) asm volatile("mbarrier.arrive.expect_tx.shared.b64 _, [%0], %1;" :: "r"(a), "r"(b) : "memory")
#define MBARRIVE(a)   asm volatile("mbarrier.arrive.shared.b64 _, [%0];" :: "r"(a) : "memory")

#define MBAR_WAIT(mbar, ph) do {                                             \
    uint32_t _m = (mbar); uint32_t _p = (ph); uint32_t _ok;                  \
    asm volatile("{\n\t.reg .pred p;\n\t"                                    \
        "mbarrier.try_wait.parity.acquire.cta.shared::cta.b64 p, [%1], %2;\n\t" \
        "selp.b32 %0, 1, 0, p;\n\t}" : "=r"(_ok) : "r"(_m), "r"(_p) : "memory"); \
    while (!_ok) {                                                           \
        asm volatile("{\n\t.reg .pred p;\n\t"                                \
            "mbarrier.try_wait.parity.acquire.cta.shared::cta.b64 p, [%1], %2, 0x989680;\n\t" \
            "selp.b32 %0, 1, 0, p;\n\t}" : "=r"(_ok) : "r"(_m), "r"(_p) : "memory"); \
    }                                                                        \
} while (0)

__device__ __forceinline__ void bulk_g2s(uint32_t dst, const void* src, uint32_t bytes, uint32_t mbar) {
    asm volatile("cp.async.bulk.shared::cluster.global.mbarrier::complete_tx::bytes [%0], [%1], %2, [%3];"
                 :: "r"(dst), "l"(src), "r"(bytes), "r"(mbar) : "memory");
}

#define MMA_BF16(acc, a, b)                                                  \
    asm volatile("mma.sync.aligned.m16n8k16.row.col.f32.bf16.bf16.f32 "      \
                 "{%0,%1,%2,%3},{%4,%5,%6,%7},{%8,%9},{%0,%1,%2,%3};"        \
                 : "+f"((acc)[0]), "+f"((acc)[1]), "+f"((acc)[2]), "+f"((acc)[3]) \
                 : "r"((a)[0]), "r"((a)[1]), "r"((a)[2]), "r"((a)[3]),       \
                   "r"((b)[0]), "r"((b)[1]))

// ---------------------------------------------------------------------------
// prep_w: W [4096][1090] fp32 -> blocked split-bf16 images
// grid (128 ntiles, 36 kb), 128 threads
// ---------------------------------------------------------------------------
__global__ void prep_w(const float* __restrict__ W) {
    int nt = blockIdx.x, kb = blockIdx.y;
    size_t base = ((size_t)(nt * NKB + kb)) * 32 * ROWB;
    for (int i = threadIdx.x; i < 32 * ROWB; i += 128) {
        int nloc = i / ROWB, kk = i % ROWB;
        int n = nt * 32 + nloc;
        int k = kb * 32 + kk;
        float v = (kk < 32 && k < KTOT) ? W[(size_t)n * KTOT + k] : 0.0f;
        __nv_bfloat16 hi = __float2bfloat16_rn(v);
        float r = v - __bfloat162float(hi);
        g_Whi[base + i] = hi;
        g_Wlo[base + i] = __float2bfloat16_rn(r);
    }
}

// ---------------------------------------------------------------------------
// init_pack: X image for step 0 (incl. pads), states
// grid B_, 128 threads
// ---------------------------------------------------------------------------
__global__ void init_pack(const float* __restrict__ z0, const float* __restrict__ c0,
                          const float* __restrict__ rnn_input) {
    int b = blockIdx.x;
    for (int i = threadIdx.x; i < NKB * ROWB; i += 128) {
        int kb = i / ROWB, kk = i % ROWB;
        int k = kb * 32 + kk;
        float v = 0.0f;
        if (kk < 32) {
            if (k < SD_)            v = z0[b * ZW + k];
            else if (k < SD_ + IN_) v = rnn_input[((size_t)b * S_) * IN_ + (k - SD_)];
            else if (k < KTOT)      v = z0[b * ZW + SD_ + (k - (SD_ + IN_))];
        }
        size_t idx = ((size_t)kb * 128 + b) * ROWB + kk;
        __nv_bfloat16 hi = __float2bfloat16_rn(v);
        float r = v - __bfloat162float(hi);
        g_Xhi[idx] = hi;
        g_Xlo[idx] = __float2bfloat16_rn(r);
    }
    for (int n = threadIdx.x; n < H_; n += 128)
        g_cstate[b * H_ + n] = c0[b * ZW + SD_ + n];
    if (threadIdx.x < 2) g_xstate[b * 2 + threadIdx.x] = z0[b * ZW + threadIdx.x];
}

// ---------------------------------------------------------------------------
// gates_hmma: C[128][4096] = Xsplit @ Wsplit^T via bf16 HMMA (3-term split)
// grid = 128 CTAs (32 gate-cols each), 128 threads (4 warps, 32x32 per warp)
// Term-major MMA ordering: each accumulator reused only every 8 MMAs,
// breaking the RAW chains that stalled the single warp per SMSP.
// ---------------------------------------------------------------------------
__global__ void __launch_bounds__(128, 1)
gates_hmma(int nt_dummy) {
    extern __shared__ char dsm[];
    uint32_t ub = smem_u32(dsm);
    const int nt  = blockIdx.x;
    const int tid = threadIdx.x;
    const int wid = tid >> 5;
    const int lane = tid & 31;
    const int lr = lane >> 2, lc = lane & 3;
    const int wm = wid * 32;

    uint32_t mb_full[2]  = {ub + 0,  ub + 8};
    uint32_t mb_empty[2] = {ub + 16, ub + 24};
    char* tiles = dsm + 128;

    if (tid == 0) {
        MBINIT(mb_full[0], 1);  MBINIT(mb_full[1], 1);
        MBINIT(mb_empty[0], 128); MBINIT(mb_empty[1], 128);
        asm volatile("fence.proxy.async.shared::cta;" ::: "memory");
    }
    __syncthreads();

    // Prologue: issue kb = 0, 1
    if (tid == 0) {
#pragma unroll
        for (int kb = 0; kb < 2; kb++) {
            int st = kb;
            uint32_t sb = ub + 128 + st * STAGE_BYTES;
            MBEXPECT(mb_full[st], STAGE_BYTES);
            bulk_g2s(sb,                      (const char*)g_Xhi + (size_t)kb * XBLK_BYTES, XBLK_BYTES, mb_full[st]);
            bulk_g2s(sb + XBLK_BYTES,         (const char*)g_Xlo + (size_t)kb * XBLK_BYTES, XBLK_BYTES, mb_full[st]);
            size_t woff = (size_t)(nt * NKB + kb) * WBLK_BYTES;
            bulk_g2s(sb + 2 * XBLK_BYTES,               (const char*)g_Whi + woff, WBLK_BYTES, mb_full[st]);
            bulk_g2s(sb + 2 * XBLK_BYTES + WBLK_BYTES,  (const char*)g_Wlo + woff, WBLK_BYTES, mb_full[st]);
        }
    }

    float acc[2][4][4];
#pragma unroll
    for (int mi = 0; mi < 2; mi++)
#pragma unroll
        for (int ni = 0; ni < 4; ni++)
#pragma unroll
            for (int e = 0; e < 4; e++) acc[mi][ni][e] = 0.0f;

    int fph[2] = {0, 0}, eph[2] = {0, 0};

    for (int kb = 0; kb < NKB; kb++) {
        int st = kb & 1;
        char* sx_hi = tiles + st * STAGE_BYTES;
        char* sx_lo = sx_hi + XBLK_BYTES;
        char* sw_hi = sx_hi + 2 * XBLK_BYTES;
        char* sw_lo = sw_hi + WBLK_BYTES;

        MBAR_WAIT(mb_full[st], fph[st]); fph[st] ^= 1;

#pragma unroll
        for (int ks = 0; ks < 2; ks++) {
            uint32_t ahi[2][4], alo[2][4], bhi[4][2], blo[4][2];
#pragma unroll
            for (int mi = 0; mi < 2; mi++) {
                int o = (wm + mi * 16 + lr) * 80 + ks * 32 + lc * 4;
                ahi[mi][0] = *(const uint32_t*)(sx_hi + o);
                ahi[mi][1] = *(const uint32_t*)(sx_hi + o + 640);
                ahi[mi][2] = *(const uint32_t*)(sx_hi + o + 16);
                ahi[mi][3] = *(const uint32_t*)(sx_hi + o + 656);
                alo[mi][0] = *(const uint32_t*)(sx_lo + o);
                alo[mi][1] = *(const uint32_t*)(sx_lo + o + 640);
                alo[mi][2] = *(const uint32_t*)(sx_lo + o + 16);
                alo[mi][3] = *(const uint32_t*)(sx_lo + o + 656);
            }
#pragma unroll
            for (int ni = 0; ni < 4; ni++) {
                int o = (ni * 8 + lr) * 80 + ks * 32 + lc * 4;
                bhi[ni][0] = *(const uint32_t*)(sw_hi + o);
                bhi[ni][1] = *(const uint32_t*)(sw_hi + o + 16);
                blo[ni][0] = *(const uint32_t*)(sw_lo + o);
                blo[ni][1] = *(const uint32_t*)(sw_lo + o + 16);
            }
            // term-major: 8 independent MMAs between accumulator reuses
#pragma unroll
            for (int mi = 0; mi < 2; mi++)
#pragma unroll
                for (int ni = 0; ni < 4; ni++)
                    MMA_BF16(acc[mi][ni], ahi[mi], bhi[ni]);
#pragma unroll
            for (int mi = 0; mi < 2; mi++)
#pragma unroll
                for (int ni = 0; ni < 4; ni++)
                    MMA_BF16(acc[mi][ni], ahi[mi], blo[ni]);
#pragma unroll
            for (int mi = 0; mi < 2; mi++)
#pragma unroll
                for (int ni = 0; ni < 4; ni++)
                    MMA_BF16(acc[mi][ni], alo[mi], bhi[ni]);
        }

        MBARRIVE(mb_empty[st]);

        if (tid == 0 && kb + 2 < NKB) {
            MBAR_WAIT(mb_empty[st], eph[st]); eph[st] ^= 1;
            int kn = kb + 2;
            uint32_t sb = ub + 128 + st * STAGE_BYTES;
            MBEXPECT(mb_full[st], STAGE_BYTES);
            bulk_g2s(sb,                      (const char*)g_Xhi + (size_t)kn * XBLK_BYTES, XBLK_BYTES, mb_full[st]);
            bulk_g2s(sb + XBLK_BYTES,         (const char*)g_Xlo + (size_t)kn * XBLK_BYTES, XBLK_BYTES, mb_full[st]);
            size_t woff = (size_t)(nt * NKB + kn) * WBLK_BYTES;
            bulk_g2s(sb + 2 * XBLK_BYTES,               (const char*)g_Whi + woff, WBLK_BYTES, mb_full[st]);
            bulk_g2s(sb + 2 * XBLK_BYTES + WBLK_BYTES,  (const char*)g_Wlo + woff, WBLK_BYTES, mb_full[st]);
        }
    }

    // Store accumulators
    const int n0 = nt * 32;
#pragma unroll
    for (int mi = 0; mi < 2; mi++) {
        int r0 = wm + mi * 16 + lr;
#pragma unroll
        for (int ni = 0; ni < 4; ni++) {
            int col = n0 + ni * 8 + lc * 2;
            g_gates[(size_t)r0 * NG + col]           = acc[mi][ni][0];
            g_gates[(size_t)r0 * NG + col + 1]       = acc[mi][ni][1];
            g_gates[(size_t)(r0 + 8) * NG + col]     = acc[mi][ni][2];
            g_gates[(size_t)(r0 + 8) * NG + col + 1] = acc[mi][ni][3];
        }
    }
}

// ---------------------------------------------------------------------------
// Pointwise step: LSTM cell + Wa/Wx dots + ODE mix + staging (fast-math)
// grid = B_, 256 threads
// ---------------------------------------------------------------------------
__global__ void __launch_bounds__(256)
step_pointwise(const float* __restrict__ WUb,
               const float* __restrict__ Wa, const float* __restrict__ Wab,
               const float* __restrict__ Wx, const float* __restrict__ Wxb,
               const float* __restrict__ Amat, const float* __restrict__ tau,
               const float* __restrict__ rnn_input,
               float* __restrict__ out, int s) {
    const int b = blockIdx.x;
    const int tid = threadIdx.x;

    const float* gb = g_gates + (size_t)b * NG;
    float* outz = out + ((size_t)b * S_ + s) * ZW;

    float wa0 = 0.f, wa1 = 0.f, wx0 = 0.f, wx1 = 0.f;

#pragma unroll
    for (int j = 0; j < 4; j++) {
        int n = tid + j * 256;
        float i_ = gb[n]          + WUb[n];
        float f_ = gb[H_ + n]     + WUb[H_ + n];
        float g_ = gb[2 * H_ + n] + WUb[2 * H_ + n];
        float o_ = gb[3 * H_ + n] + WUb[3 * H_ + n];
        float c  = g_cstate[b * H_ + n];
        float cn = sigf(f_) * c + sigf(i_) * tanhfast(g_);
        float hn = sigf(o_) * tanhfast(cn);
        g_cstate[b * H_ + n] = cn;
        store_x_hilo(b, SD_ + IN_ + n, hn);
        outz[SD_ + n] = hn;
        wa0 += Wa[n] * hn;       wa1 += Wa[H_ + n] * hn;
        wx0 += Wx[n] * hn;       wx1 += Wx[H_ + n] * hn;
    }

    __shared__ float red[8][4];
    unsigned mask = 0xffffffffu;
#pragma unroll
    for (int off = 16; off > 0; off >>= 1) {
        wa0 += __shfl_down_sync(mask, wa0, off);
        wa1 += __shfl_down_sync(mask, wa1, off);
        wx0 += __shfl_down_sync(mask, wx0, off);
        wx1 += __shfl_down_sync(mask, wx1, off);
    }
    if ((tid & 31) == 0) {
        red[tid >> 5][0] = wa0; red[tid >> 5][1] = wa1;
        red[tid >> 5][2] = wx0; red[tid >> 5][3] = wx1;
    }
    __syncthreads();

    if (tid == 0) {
        float s0 = 0.f, s1 = 0.f, s2 = 0.f, s3 = 0.f;
#pragma unroll
        for (int w = 0; w < 8; w++) {
            s0 += red[w][0]; s1 += red[w][1]; s2 += red[w][2]; s3 += red[w][3];
        }
        float xp0 = g_xstate[b * 2 + 0];
        float xp1 = g_xstate[b * 2 + 1];
        float t   = tau[b * S_ + s];
        float xm0 = xp0 + t * (Amat[0] * xp0 + Amat[1] * xp1);
        float xm1 = xp1 + t * (Amat[2] * xp0 + Amat[3] * xp1);
        float a0  = sigf(s0 + Wab[0]);
        float a1  = sigf(s1 + Wab[1]);
        float xt0 = s2 + Wxb[0];
        float xt1 = s3 + Wxb[1];
        float xn0 = a0 * xm0 + (1.0f - a0) * xt0;
        float xn1 = a1 * xm1 + (1.0f - a1) * xt1;
        g_xstate[b * 2 + 0] = xn0;
        g_xstate[b * 2 + 1] = xn1;
        store_x_hilo(b, 0, xn0);
        store_x_hilo(b, 1, xn1);
        outz[0] = xn0;
        outz[1] = xn1;
        float* cf = out + OUT_COEF + ((size_t)b * S_ + s) * SD_;
        cf[0] = a0;
        cf[1] = a1;
    }

    if (s + 1 < S_ && tid < IN_) {
        store_x_hilo(b, SD_ + tid,
                     rnn_input[((size_t)b * S_ + (s + 1)) * IN_ + tid]);
    }
}

// ---------------------------------------------------------------------------
// Final: z_f = outputs[:, -1, :], c_z_f = [c0[:, :2], c_final]
// ---------------------------------------------------------------------------
__global__ void final_out(const float* __restrict__ c0, float* __restrict__ out) {
    int b = blockIdx.x;
    float* zf  = out + OUT_ZF  + (size_t)b * ZW;
    float* czf = out + OUT_CZF + (size_t)b * ZW;
    const float* last = out + ((size_t)b * S_ + (S_ - 1)) * ZW;
    for (int k = threadIdx.x; k < ZW; k += 256) {
        zf[k] = last[k];
        czf[k] = (k < SD_) ? c0[b * ZW + k] : g_cstate[b * H_ + (k - SD_)];
    }
}

// ---------------------------------------------------------------------------
extern "C" void kernel_launch(void* const* d_in, const int* in_sizes, int n_in,
                              void* d_out, int out_size) {
    const float* rnn_input = (const float*)d_in[0];
    const float* z0        = (const float*)d_in[1];
    const float* c0        = (const float*)d_in[2];
    const float* tau       = (const float*)d_in[3];
    const float* A         = (const float*)d_in[4];
    const float* WU_w      = (const float*)d_in[5];
    const float* WU_b      = (const float*)d_in[6];
    const float* Wa_w      = (const float*)d_in[7];
    const float* Wa_b      = (const float*)d_in[8];
    const float* Wx_w      = (const float*)d_in[9];
    const float* Wx_b      = (const float*)d_in[10];
    float* out = (float*)d_out;

    cudaFuncSetAttribute(gates_hmma, cudaFuncAttributeMaxDynamicSharedMemorySize, SMEM_DYN);

    prep_w<<<dim3(128, NKB), 128>>>(WU_w);
    init_pack<<<B_, 128>>>(z0, c0, rnn_input);
    for (int s = 0; s < S_; s++) {
        gates_hmma<<<128, 128, SMEM_DYN>>>(0);
        step_pointwise<<<B_, 256>>>(WU_b, Wa_w, Wa_b, Wx_w, Wx_b, A, tau,
                                    rnn_input, out, s);
    }
    final_out<<<B_, 256>>>(c0, out);
}

// round 7
// speedup vs baseline: 1.4751x; 1.0819x over previous
#include <cuda_runtime.h>
#include <cuda_bf16.h>
#include <cstdint>
#include <cstddef>

// ---------------------------------------------------------------------------
// Problem constants
// ---------------------------------------------------------------------------
#define B_   128
#define S_   256
#define H_   1024
#define IN_  64
#define SD_  2
#define KTOT 1090
#define NKB  36              // K blocks of 32 (KPAD = 1152)
#define ZW   (SD_ + H_)      // 1026
#define NG   4096

#define OUT_ZF   ((size_t)B_ * S_ * ZW)
#define OUT_CZF  (OUT_ZF + (size_t)B_ * ZW)
#define OUT_COEF (OUT_CZF + (size_t)B_ * ZW)

// Blocked layouts: rows padded to 40 bf16 (80 B) for conflict-free LDS
#define ROWB 40
#define XBLK_BYTES  (128 * ROWB * 2)          // 10240 per K-block
#define WBLK_BYTES  (32 * ROWB * 2)           // 2560 per (ntile, kb)
#define STAGE_BYTES (2 * XBLK_BYTES + 2 * WBLK_BYTES)   // 25600
#define SMEM_DYN    (128 + 2 * STAGE_BYTES)             // 51328

// ---------------------------------------------------------------------------
// Device-global scratch
// ---------------------------------------------------------------------------
__device__ __align__(128) __nv_bfloat16 g_Xhi[(size_t)NKB * 128 * ROWB];
__device__ __align__(128) __nv_bfloat16 g_Xlo[(size_t)NKB * 128 * ROWB];
__device__ __align__(128) __nv_bfloat16 g_Whi[(size_t)128 * NKB * 32 * ROWB];
__device__ __align__(128) __nv_bfloat16 g_Wlo[(size_t)128 * NKB * 32 * ROWB];
__device__ float g_gates[(size_t)B_ * NG];
__device__ float g_cstate[B_ * H_];
__device__ float g_xstate[B_ * 2];

// ---------------------------------------------------------------------------
// Helpers
// ---------------------------------------------------------------------------
__device__ __forceinline__ float sigf(float x) { return 1.0f / (1.0f + __expf(-x)); }
__device__ __forceinline__ float tanhfast(float x) { return 2.0f / (1.0f + __expf(-2.0f * x)) - 1.0f; }

__device__ __forceinline__ void store_x_hilo(int m, int k, float v) {
    int kb = k >> 5, kk = k & 31;
    size_t idx = ((size_t)kb * 128 + m) * ROWB + kk;
    __nv_bfloat16 hi = __float2bfloat16_rn(v);
    float r = v - __bfloat162float(hi);
    g_Xhi[idx] = hi;
    g_Xlo[idx] = __float2bfloat16_rn(r);
}

__device__ __forceinline__ uint32_t smem_u32(const void* p) {
    uint32_t a;
    asm("{ .reg .u64 t; cvta.to.shared.u64 t, %1; cvt.u32.u64 %0, t; }" : "=r"(a) : "l"(p));
    return a;
}

#define MBINIT(a, c)  asm volatile("mbarrier.init.shared.b64 [%0], %1;" :: "r"(a), "r"(c) : "memory")
#define MBEXPECT(a,b) asm volatile("mbarrier.arrive.expect_tx.shared.b64 _, [%0], %1;" :: "r"(a), "r"(b) : "memory")
#define MBARRIVE(a)   asm volatile("mbarrier.arrive.shared.b64 _, [%0];" :: "r"(a) : "memory")

#define MBAR_WAIT(mbar, ph) do {                                             \
    uint32_t _m = (mbar); uint32_t _p = (ph); uint32_t _ok;                  \
    asm volatile("{\n\t.reg .pred p;\n\t"                                    \
        "mbarrier.try_wait.parity.acquire.cta.shared::cta.b64 p, [%1], %2;\n\t" \
        "selp.b32 %0, 1, 0, p;\n\t}" : "=r"(_ok) : "r"(_m), "r"(_p) : "memory"); \
    while (!_ok) {                                                           \
        asm volatile("{\n\t.reg .pred p;\n\t"                                \
            "mbarrier.try_wait.parity.acquire.cta.shared::cta.b64 p, [%1], %2, 0x989680;\n\t" \
            "selp.b32 %0, 1, 0, p;\n\t}" : "=r"(_ok) : "r"(_m), "r"(_p) : "memory"); \
    }                                                                        \
} while (0)

__device__ __forceinline__ void bulk_g2s(uint32_t dst, const void* src, uint32_t bytes, uint32_t mbar) {
    asm volatile("cp.async.bulk.shared::cluster.global.mbarrier::complete_tx::bytes [%0], [%1], %2, [%3];"
                 :: "r"(dst), "l"(src), "r"(bytes), "r"(mbar) : "memory");
}

#define MMA_BF16(acc, a, b)                                                  \
    asm volatile("mma.sync.aligned.m16n8k16.row.col.f32.bf16.bf16.f32 "      \
                 "{%0,%1,%2,%3},{%4,%5,%6,%7},{%8,%9},{%0,%1,%2,%3};"        \
                 : "+f"((acc)[0]), "+f"((acc)[1]), "+f"((acc)[2]), "+f"((acc)[3]) \
                 : "r"((a)[0]), "r"((a)[1]), "r"((a)[2]), "r"((a)[3]),       \
                   "r"((b)[0]), "r"((b)[1]))

// ---------------------------------------------------------------------------
// prep_w: W [4096][1090] fp32 -> blocked split-bf16 images
// grid (128 ntiles, 36 kb), 128 threads
// ---------------------------------------------------------------------------
__global__ void prep_w(const float* __restrict__ W) {
    int nt = blockIdx.x, kb = blockIdx.y;
    size_t base = ((size_t)(nt * NKB + kb)) * 32 * ROWB;
    for (int i = threadIdx.x; i < 32 * ROWB; i += 128) {
        int nloc = i / ROWB, kk = i % ROWB;
        int n = nt * 32 + nloc;
        int k = kb * 32 + kk;
        float v = (kk < 32 && k < KTOT) ? W[(size_t)n * KTOT + k] : 0.0f;
        __nv_bfloat16 hi = __float2bfloat16_rn(v);
        float r = v - __bfloat162float(hi);
        g_Whi[base + i] = hi;
        g_Wlo[base + i] = __float2bfloat16_rn(r);
    }
}

// ---------------------------------------------------------------------------
// init_pack: X image for step 0 (incl. pads), states
// grid B_, 128 threads
// ---------------------------------------------------------------------------
__global__ void init_pack(const float* __restrict__ z0, const float* __restrict__ c0,
                          const float* __restrict__ rnn_input) {
    int b = blockIdx.x;
    for (int i = threadIdx.x; i < NKB * ROWB; i += 128) {
        int kb = i / ROWB, kk = i % ROWB;
        int k = kb * 32 + kk;
        float v = 0.0f;
        if (kk < 32) {
            if (k < SD_)            v = z0[b * ZW + k];
            else if (k < SD_ + IN_) v = rnn_input[((size_t)b * S_) * IN_ + (k - SD_)];
            else if (k < KTOT)      v = z0[b * ZW + SD_ + (k - (SD_ + IN_))];
        }
        size_t idx = ((size_t)kb * 128 + b) * ROWB + kk;
        __nv_bfloat16 hi = __float2bfloat16_rn(v);
        float r = v - __bfloat162float(hi);
        g_Xhi[idx] = hi;
        g_Xlo[idx] = __float2bfloat16_rn(r);
    }
    for (int n = threadIdx.x; n < H_; n += 128)
        g_cstate[b * H_ + n] = c0[b * ZW + SD_ + n];
    if (threadIdx.x < 2) g_xstate[b * 2 + threadIdx.x] = z0[b * ZW + threadIdx.x];
}

// ---------------------------------------------------------------------------
// gates_hmma: C[128][4096] = Xsplit @ Wsplit^T via bf16 HMMA (3-term split)
// grid = 128 CTAs (32 gate-cols each), 128 threads (4 warps, 32x32 per warp)
// (unchanged from R6 — measured at the HMMA issue floor)
// ---------------------------------------------------------------------------
__global__ void __launch_bounds__(128, 1)
gates_hmma(int nt_dummy) {
    extern __shared__ char dsm[];
    uint32_t ub = smem_u32(dsm);
    const int nt  = blockIdx.x;
    const int tid = threadIdx.x;
    const int wid = tid >> 5;
    const int lane = tid & 31;
    const int lr = lane >> 2, lc = lane & 3;
    const int wm = wid * 32;

    uint32_t mb_full[2]  = {ub + 0,  ub + 8};
    uint32_t mb_empty[2] = {ub + 16, ub + 24};
    char* tiles = dsm + 128;

    if (tid == 0) {
        MBINIT(mb_full[0], 1);  MBINIT(mb_full[1], 1);
        MBINIT(mb_empty[0], 128); MBINIT(mb_empty[1], 128);
        asm volatile("fence.proxy.async.shared::cta;" ::: "memory");
    }
    __syncthreads();

    if (tid == 0) {
#pragma unroll
        for (int kb = 0; kb < 2; kb++) {
            int st = kb;
            uint32_t sb = ub + 128 + st * STAGE_BYTES;
            MBEXPECT(mb_full[st], STAGE_BYTES);
            bulk_g2s(sb,                      (const char*)g_Xhi + (size_t)kb * XBLK_BYTES, XBLK_BYTES, mb_full[st]);
            bulk_g2s(sb + XBLK_BYTES,         (const char*)g_Xlo + (size_t)kb * XBLK_BYTES, XBLK_BYTES, mb_full[st]);
            size_t woff = (size_t)(nt * NKB + kb) * WBLK_BYTES;
            bulk_g2s(sb + 2 * XBLK_BYTES,               (const char*)g_Whi + woff, WBLK_BYTES, mb_full[st]);
            bulk_g2s(sb + 2 * XBLK_BYTES + WBLK_BYTES,  (const char*)g_Wlo + woff, WBLK_BYTES, mb_full[st]);
        }
    }

    float acc[2][4][4];
#pragma unroll
    for (int mi = 0; mi < 2; mi++)
#pragma unroll
        for (int ni = 0; ni < 4; ni++)
#pragma unroll
            for (int e = 0; e < 4; e++) acc[mi][ni][e] = 0.0f;

    int fph[2] = {0, 0}, eph[2] = {0, 0};

    for (int kb = 0; kb < NKB; kb++) {
        int st = kb & 1;
        char* sx_hi = tiles + st * STAGE_BYTES;
        char* sx_lo = sx_hi + XBLK_BYTES;
        char* sw_hi = sx_hi + 2 * XBLK_BYTES;
        char* sw_lo = sw_hi + WBLK_BYTES;

        MBAR_WAIT(mb_full[st], fph[st]); fph[st] ^= 1;

#pragma unroll
        for (int ks = 0; ks < 2; ks++) {
            uint32_t ahi[2][4], alo[2][4], bhi[4][2], blo[4][2];
#pragma unroll
            for (int mi = 0; mi < 2; mi++) {
                int o = (wm + mi * 16 + lr) * 80 + ks * 32 + lc * 4;
                ahi[mi][0] = *(const uint32_t*)(sx_hi + o);
                ahi[mi][1] = *(const uint32_t*)(sx_hi + o + 640);
                ahi[mi][2] = *(const uint32_t*)(sx_hi + o + 16);
                ahi[mi][3] = *(const uint32_t*)(sx_hi + o + 656);
                alo[mi][0] = *(const uint32_t*)(sx_lo + o);
                alo[mi][1] = *(const uint32_t*)(sx_lo + o + 640);
                alo[mi][2] = *(const uint32_t*)(sx_lo + o + 16);
                alo[mi][3] = *(const uint32_t*)(sx_lo + o + 656);
            }
#pragma unroll
            for (int ni = 0; ni < 4; ni++) {
                int o = (ni * 8 + lr) * 80 + ks * 32 + lc * 4;
                bhi[ni][0] = *(const uint32_t*)(sw_hi + o);
                bhi[ni][1] = *(const uint32_t*)(sw_hi + o + 16);
                blo[ni][0] = *(const uint32_t*)(sw_lo + o);
                blo[ni][1] = *(const uint32_t*)(sw_lo + o + 16);
            }
#pragma unroll
            for (int mi = 0; mi < 2; mi++)
#pragma unroll
                for (int ni = 0; ni < 4; ni++)
                    MMA_BF16(acc[mi][ni], ahi[mi], bhi[ni]);
#pragma unroll
            for (int mi = 0; mi < 2; mi++)
#pragma unroll
                for (int ni = 0; ni < 4; ni++)
                    MMA_BF16(acc[mi][ni], ahi[mi], blo[ni]);
#pragma unroll
            for (int mi = 0; mi < 2; mi++)
#pragma unroll
                for (int ni = 0; ni < 4; ni++)
                    MMA_BF16(acc[mi][ni], alo[mi], bhi[ni]);
        }

        MBARRIVE(mb_empty[st]);

        if (tid == 0 && kb + 2 < NKB) {
            MBAR_WAIT(mb_empty[st], eph[st]); eph[st] ^= 1;
            int kn = kb + 2;
            uint32_t sb = ub + 128 + st * STAGE_BYTES;
            MBEXPECT(mb_full[st], STAGE_BYTES);
            bulk_g2s(sb,                      (const char*)g_Xhi + (size_t)kn * XBLK_BYTES, XBLK_BYTES, mb_full[st]);
            bulk_g2s(sb + XBLK_BYTES,         (const char*)g_Xlo + (size_t)kn * XBLK_BYTES, XBLK_BYTES, mb_full[st]);
            size_t woff = (size_t)(nt * NKB + kn) * WBLK_BYTES;
            bulk_g2s(sb + 2 * XBLK_BYTES,               (const char*)g_Whi + woff, WBLK_BYTES, mb_full[st]);
            bulk_g2s(sb + 2 * XBLK_BYTES + WBLK_BYTES,  (const char*)g_Wlo + woff, WBLK_BYTES, mb_full[st]);
        }
    }

    const int n0 = nt * 32;
#pragma unroll
    for (int mi = 0; mi < 2; mi++) {
        int r0 = wm + mi * 16 + lr;
#pragma unroll
        for (int ni = 0; ni < 4; ni++) {
            int col = n0 + ni * 8 + lc * 2;
            g_gates[(size_t)r0 * NG + col]           = acc[mi][ni][0];
            g_gates[(size_t)r0 * NG + col + 1]       = acc[mi][ni][1];
            g_gates[(size_t)(r0 + 8) * NG + col]     = acc[mi][ni][2];
            g_gates[(size_t)(r0 + 8) * NG + col + 1] = acc[mi][ni][3];
        }
    }
}

// ---------------------------------------------------------------------------
// Pointwise step: 1024 threads/block (32 warps/SM), 1 unit per thread.
// grid = B_, 1024 threads
// ---------------------------------------------------------------------------
__global__ void __launch_bounds__(1024, 1)
step_pointwise(const float* __restrict__ WUb,
               const float* __restrict__ Wa, const float* __restrict__ Wab,
               const float* __restrict__ Wx, const float* __restrict__ Wxb,
               const float* __restrict__ Amat, const float* __restrict__ tau,
               const float* __restrict__ rnn_input,
               float* __restrict__ out, int s) {
    const int b = blockIdx.x;
    const int tid = threadIdx.x;
    const int lane = tid & 31;
    const int wid = tid >> 5;

    const float* gb = g_gates + (size_t)b * NG;
    float* outz = out + ((size_t)b * S_ + s) * ZW;

    const int n = tid;  // unit index 0..1023
    float i_ = gb[n]          + WUb[n];
    float f_ = gb[H_ + n]     + WUb[H_ + n];
    float g_ = gb[2 * H_ + n] + WUb[2 * H_ + n];
    float o_ = gb[3 * H_ + n] + WUb[3 * H_ + n];
    float c  = g_cstate[b * H_ + n];
    float cn = sigf(f_) * c + sigf(i_) * tanhfast(g_);
    float hn = sigf(o_) * tanhfast(cn);
    g_cstate[b * H_ + n] = cn;
    store_x_hilo(b, SD_ + IN_ + n, hn);
    outz[SD_ + n] = hn;

    float wa0 = Wa[n] * hn;
    float wa1 = Wa[H_ + n] * hn;
    float wx0 = Wx[n] * hn;
    float wx1 = Wx[H_ + n] * hn;

    __shared__ float red[32][4];
    unsigned mask = 0xffffffffu;
#pragma unroll
    for (int off = 16; off > 0; off >>= 1) {
        wa0 += __shfl_down_sync(mask, wa0, off);
        wa1 += __shfl_down_sync(mask, wa1, off);
        wx0 += __shfl_down_sync(mask, wx0, off);
        wx1 += __shfl_down_sync(mask, wx1, off);
    }
    if (lane == 0) {
        red[wid][0] = wa0; red[wid][1] = wa1;
        red[wid][2] = wx0; red[wid][3] = wx1;
    }
    __syncthreads();

    if (wid == 0) {
        float s0 = red[lane][0], s1 = red[lane][1];
        float s2 = red[lane][2], s3 = red[lane][3];
#pragma unroll
        for (int off = 16; off > 0; off >>= 1) {
            s0 += __shfl_down_sync(mask, s0, off);
            s1 += __shfl_down_sync(mask, s1, off);
            s2 += __shfl_down_sync(mask, s2, off);
            s3 += __shfl_down_sync(mask, s3, off);
        }
        if (lane == 0) {
            float xp0 = g_xstate[b * 2 + 0];
            float xp1 = g_xstate[b * 2 + 1];
            float t   = tau[b * S_ + s];
            float xm0 = xp0 + t * (Amat[0] * xp0 + Amat[1] * xp1);
            float xm1 = xp1 + t * (Amat[2] * xp0 + Amat[3] * xp1);
            float a0  = sigf(s0 + Wab[0]);
            float a1  = sigf(s1 + Wab[1]);
            float xt0 = s2 + Wxb[0];
            float xt1 = s3 + Wxb[1];
            float xn0 = a0 * xm0 + (1.0f - a0) * xt0;
            float xn1 = a1 * xm1 + (1.0f - a1) * xt1;
            g_xstate[b * 2 + 0] = xn0;
            g_xstate[b * 2 + 1] = xn1;
            store_x_hilo(b, 0, xn0);
            store_x_hilo(b, 1, xn1);
            outz[0] = xn0;
            outz[1] = xn1;
            float* cf = out + OUT_COEF + ((size_t)b * S_ + s) * SD_;
            cf[0] = a0;
            cf[1] = a1;
        }
    }

    if (s + 1 < S_ && tid >= 64 && tid < 64 + IN_) {
        int u = tid - 64;
        store_x_hilo(b, SD_ + u,
                     rnn_input[((size_t)b * S_ + (s + 1)) * IN_ + u]);
    }
}

// ---------------------------------------------------------------------------
// Final: z_f = outputs[:, -1, :], c_z_f = [c0[:, :2], c_final]
// ---------------------------------------------------------------------------
__global__ void final_out(const float* __restrict__ c0, float* __restrict__ out) {
    int b = blockIdx.x;
    float* zf  = out + OUT_ZF  + (size_t)b * ZW;
    float* czf = out + OUT_CZF + (size_t)b * ZW;
    const float* last = out + ((size_t)b * S_ + (S_ - 1)) * ZW;
    for (int k = threadIdx.x; k < ZW; k += 256) {
        zf[k] = last[k];
        czf[k] = (k < SD_) ? c0[b * ZW + k] : g_cstate[b * H_ + (k - SD_)];
    }
}

// ---------------------------------------------------------------------------
extern "C" void kernel_launch(void* const* d_in, const int* in_sizes, int n_in,
                              void* d_out, int out_size) {
    const float* rnn_input = (const float*)d_in[0];
    const float* z0        = (const float*)d_in[1];
    const float* c0        = (const float*)d_in[2];
    const float* tau       = (const float*)d_in[3];
    const float* A         = (const float*)d_in[4];
    const float* WU_w      = (const float*)d_in[5];
    const float* WU_b      = (const float*)d_in[6];
    const float* Wa_w      = (const float*)d_in[7];
    const float* Wa_b      = (const float*)d_in[8];
    const float* Wx_w      = (const float*)d_in[9];
    const float* Wx_b      = (const float*)d_in[10];
    float* out = (float*)d_out;

    cudaFuncSetAttribute(gates_hmma, cudaFuncAttributeMaxDynamicSharedMemorySize, SMEM_DYN);

    prep_w<<<dim3(128, NKB), 128>>>(WU_w);
    init_pack<<<B_, 128>>>(z0, c0, rnn_input);
    for (int s = 0; s < S_; s++) {
        gates_hmma<<<128, 128, SMEM_DYN>>>(0);
        step_pointwise<<<B_, 1024>>>(WU_b, Wa_w, Wa_b, Wx_w, Wx_b, A, tau,
                                     rnn_input, out, s);
    }
    final_out<<<B_, 256>>>(c0, out);
}

// round 8
// speedup vs baseline: 2.0686x; 1.4023x over previous
#include <cuda_runtime.h>
#include <cuda_bf16.h>
#include <cstdint>
#include <cstddef>

// ---------------------------------------------------------------------------
// Problem constants
// ---------------------------------------------------------------------------
#define B_   128
#define S_   256
#define H_   1024
#define IN_  64
#define SD_  2
#define KTOT 1090
#define NKB  36              // K blocks of 32 (KPAD = 1152)
#define NKH  18              // K blocks per K-split half
#define ZW   (SD_ + H_)      // 1026
#define NG   4096

#define OUT_ZF   ((size_t)B_ * S_ * ZW)
#define OUT_CZF  (OUT_ZF + (size_t)B_ * ZW)
#define OUT_COEF (OUT_CZF + (size_t)B_ * ZW)

// Blocked layouts: rows padded to 40 bf16 (80 B) for conflict-free LDS
#define ROWB 40
#define XBLK_BYTES  (128 * ROWB * 2)          // 10240 per K-block
#define WBLK_BYTES  (64 * ROWB * 2)           // 5120 per (ntile64, kb)
#define STAGE_BYTES (2 * XBLK_BYTES + 2 * WBLK_BYTES)   // 30720
#define SMEM_DYN    (128 + 2 * STAGE_BYTES)             // 61568

// ---------------------------------------------------------------------------
// Device-global scratch
// ---------------------------------------------------------------------------
__device__ __align__(128) __nv_bfloat16 g_Xhi[(size_t)NKB * 128 * ROWB];
__device__ __align__(128) __nv_bfloat16 g_Xlo[(size_t)NKB * 128 * ROWB];
__device__ __align__(128) __nv_bfloat16 g_Whi[(size_t)64 * NKB * 64 * ROWB];
__device__ __align__(128) __nv_bfloat16 g_Wlo[(size_t)64 * NKB * 64 * ROWB];
__device__ float g_gates[2][(size_t)B_ * NG];   // two K-split partials
__device__ float g_cstate[B_ * H_];
__device__ float g_xstate[B_ * 2];

// ---------------------------------------------------------------------------
// Helpers
// ---------------------------------------------------------------------------
__device__ __forceinline__ float sigf(float x) { return 1.0f / (1.0f + __expf(-x)); }
__device__ __forceinline__ float tanhfast(float x) { return 2.0f / (1.0f + __expf(-2.0f * x)) - 1.0f; }

__device__ __forceinline__ void store_x_hilo(int m, int k, float v) {
    int kb = k >> 5, kk = k & 31;
    size_t idx = ((size_t)kb * 128 + m) * ROWB + kk;
    __nv_bfloat16 hi = __float2bfloat16_rn(v);
    float r = v - __bfloat162float(hi);
    g_Xhi[idx] = hi;
    g_Xlo[idx] = __float2bfloat16_rn(r);
}

__device__ __forceinline__ uint32_t smem_u32(const void* p) {
    uint32_t a;
    asm("{ .reg .u64 t; cvta.to.shared.u64 t, %1; cvt.u32.u64 %0, t; }" : "=r"(a) : "l"(p));
    return a;
}

#define MBINIT(a, c)  asm volatile("mbarrier.init.shared.b64 [%0], %1;" :: "r"(a), "r"(c) : "memory")
#define MBEXPECT(a,b) asm volatile("mbarrier.arrive.expect_tx.shared.b64 _, [%0], %1;" :: "r"(a), "r"(b) : "memory")
#define MBARRIVE(a)   asm volatile("mbarrier.arrive.shared.b64 _, [%0];" :: "r"(a) : "memory")

#define MBAR_WAIT(mbar, ph) do {                                             \
    uint32_t _m = (mbar); uint32_t _p = (ph); uint32_t _ok;                  \
    asm volatile("{\n\t.reg .pred p;\n\t"                                    \
        "mbarrier.try_wait.parity.acquire.cta.shared::cta.b64 p, [%1], %2;\n\t" \
        "selp.b32 %0, 1, 0, p;\n\t}" : "=r"(_ok) : "r"(_m), "r"(_p) : "memory"); \
    while (!_ok) {                                                           \
        asm volatile("{\n\t.reg .pred p;\n\t"                                \
            "mbarrier.try_wait.parity.acquire.cta.shared::cta.b64 p, [%1], %2, 0x989680;\n\t" \
            "selp.b32 %0, 1, 0, p;\n\t}" : "=r"(_ok) : "r"(_m), "r"(_p) : "memory"); \
    }                                                                        \
} while (0)

__device__ __forceinline__ void bulk_g2s(uint32_t dst, const void* src, uint32_t bytes, uint32_t mbar) {
    asm volatile("cp.async.bulk.shared::cluster.global.mbarrier::complete_tx::bytes [%0], [%1], %2, [%3];"
                 :: "r"(dst), "l"(src), "r"(bytes), "r"(mbar) : "memory");
}

#define MMA_BF16(acc, a, b)                                                  \
    asm volatile("mma.sync.aligned.m16n8k16.row.col.f32.bf16.bf16.f32 "      \
                 "{%0,%1,%2,%3},{%4,%5,%6,%7},{%8,%9},{%0,%1,%2,%3};"        \
                 : "+f"((acc)[0]), "+f"((acc)[1]), "+f"((acc)[2]), "+f"((acc)[3]) \
                 : "r"((a)[0]), "r"((a)[1]), "r"((a)[2]), "r"((a)[3]),       \
                   "r"((b)[0]), "r"((b)[1]))

// ---------------------------------------------------------------------------
// prep_w: W [4096][1090] fp32 -> blocked (64-col tiles) split-bf16 images
// grid (64 ntiles, 36 kb), 256 threads
// ---------------------------------------------------------------------------
__global__ void prep_w(const float* __restrict__ W) {
    int nt = blockIdx.x, kb = blockIdx.y;
    size_t base = ((size_t)(nt * NKB + kb)) * 64 * ROWB;
    for (int i = threadIdx.x; i < 64 * ROWB; i += 256) {
        int nloc = i / ROWB, kk = i % ROWB;
        int n = nt * 64 + nloc;
        int k = kb * 32 + kk;
        float v = (kk < 32 && k < KTOT) ? W[(size_t)n * KTOT + k] : 0.0f;
        __nv_bfloat16 hi = __float2bfloat16_rn(v);
        float r = v - __bfloat162float(hi);
        g_Whi[base + i] = hi;
        g_Wlo[base + i] = __float2bfloat16_rn(r);
    }
}

// ---------------------------------------------------------------------------
// init_pack: X image for step 0 (incl. pads), states
// grid B_, 128 threads
// ---------------------------------------------------------------------------
__global__ void init_pack(const float* __restrict__ z0, const float* __restrict__ c0,
                          const float* __restrict__ rnn_input) {
    int b = blockIdx.x;
    for (int i = threadIdx.x; i < NKB * ROWB; i += 128) {
        int kb = i / ROWB, kk = i % ROWB;
        int k = kb * 32 + kk;
        float v = 0.0f;
        if (kk < 32) {
            if (k < SD_)            v = z0[b * ZW + k];
            else if (k < SD_ + IN_) v = rnn_input[((size_t)b * S_) * IN_ + (k - SD_)];
            else if (k < KTOT)      v = z0[b * ZW + SD_ + (k - (SD_ + IN_))];
        }
        size_t idx = ((size_t)kb * 128 + b) * ROWB + kk;
        __nv_bfloat16 hi = __float2bfloat16_rn(v);
        float r = v - __bfloat162float(hi);
        g_Xhi[idx] = hi;
        g_Xlo[idx] = __float2bfloat16_rn(r);
    }
    for (int n = threadIdx.x; n < H_; n += 128)
        g_cstate[b * H_ + n] = c0[b * ZW + SD_ + n];
    if (threadIdx.x < 2) g_xstate[b * 2 + threadIdx.x] = z0[b * ZW + threadIdx.x];
}

// ---------------------------------------------------------------------------
// gates_hmma: partial C = Xsplit @ Wsplit^T over one K half (split-bf16 x3)
// grid = (64 ntiles, 2 ksplit), 256 threads = 8 warps (2/SMSP).
// Warp (mp, ng): rows [mp*32,+32) x cols [ng*32,+32) of this CTA's 64-col tile.
// ---------------------------------------------------------------------------
__global__ void __launch_bounds__(256, 1)
gates_hmma() {
    extern __shared__ char dsm[];
    uint32_t ub = smem_u32(dsm);
    const int nt  = blockIdx.x;
    const int ki  = blockIdx.y;          // K-split half
    const int tid = threadIdx.x;
    const int wid = tid >> 5;
    const int lane = tid & 31;
    const int lr = lane >> 2, lc = lane & 3;
    const int mp = wid & 3;              // M position (32 rows)
    const int ng = wid >> 2;             // N group (32 cols)

    uint32_t mb_full[2]  = {ub + 0,  ub + 8};
    uint32_t mb_empty[2] = {ub + 16, ub + 24};
    char* tiles = dsm + 128;

    if (tid == 0) {
        MBINIT(mb_full[0], 1);  MBINIT(mb_full[1], 1);
        MBINIT(mb_empty[0], 256); MBINIT(mb_empty[1], 256);
        asm volatile("fence.proxy.async.shared::cta;" ::: "memory");
    }
    __syncthreads();

    // Prologue: issue local kb = 0, 1
    if (tid == 0) {
#pragma unroll
        for (int kb = 0; kb < 2; kb++) {
            int kg = ki * NKH + kb;
            uint32_t sb = ub + 128 + kb * STAGE_BYTES;
            MBEXPECT(mb_full[kb], STAGE_BYTES);
            bulk_g2s(sb,              (const char*)g_Xhi + (size_t)kg * XBLK_BYTES, XBLK_BYTES, mb_full[kb]);
            bulk_g2s(sb + XBLK_BYTES, (const char*)g_Xlo + (size_t)kg * XBLK_BYTES, XBLK_BYTES, mb_full[kb]);
            size_t woff = (size_t)(nt * NKB + kg) * WBLK_BYTES;
            bulk_g2s(sb + 2 * XBLK_BYTES,              (const char*)g_Whi + woff, WBLK_BYTES, mb_full[kb]);
            bulk_g2s(sb + 2 * XBLK_BYTES + WBLK_BYTES, (const char*)g_Wlo + woff, WBLK_BYTES, mb_full[kb]);
        }
    }

    float acc[2][4][4];
#pragma unroll
    for (int mi = 0; mi < 2; mi++)
#pragma unroll
        for (int ni = 0; ni < 4; ni++)
#pragma unroll
            for (int e = 0; e < 4; e++) acc[mi][ni][e] = 0.0f;

    int fph[2] = {0, 0}, eph[2] = {0, 0};

    for (int kb = 0; kb < NKH; kb++) {
        int st = kb & 1;
        char* sx_hi = tiles + st * STAGE_BYTES;
        char* sx_lo = sx_hi + XBLK_BYTES;
        char* sw_hi = sx_hi + 2 * XBLK_BYTES;
        char* sw_lo = sw_hi + WBLK_BYTES;

        MBAR_WAIT(mb_full[st], fph[st]); fph[st] ^= 1;

#pragma unroll
        for (int ks = 0; ks < 2; ks++) {
            uint32_t ahi[2][4], alo[2][4], bhi[4][2], blo[4][2];
#pragma unroll
            for (int mi = 0; mi < 2; mi++) {
                int o = (mp * 32 + mi * 16 + lr) * 80 + ks * 32 + lc * 4;
                ahi[mi][0] = *(const uint32_t*)(sx_hi + o);
                ahi[mi][1] = *(const uint32_t*)(sx_hi + o + 640);
                ahi[mi][2] = *(const uint32_t*)(sx_hi + o + 16);
                ahi[mi][3] = *(const uint32_t*)(sx_hi + o + 656);
                alo[mi][0] = *(const uint32_t*)(sx_lo + o);
                alo[mi][1] = *(const uint32_t*)(sx_lo + o + 640);
                alo[mi][2] = *(const uint32_t*)(sx_lo + o + 16);
                alo[mi][3] = *(const uint32_t*)(sx_lo + o + 656);
            }
#pragma unroll
            for (int ni = 0; ni < 4; ni++) {
                int o = (ng * 32 + ni * 8 + lr) * 80 + ks * 32 + lc * 4;
                bhi[ni][0] = *(const uint32_t*)(sw_hi + o);
                bhi[ni][1] = *(const uint32_t*)(sw_hi + o + 16);
                blo[ni][0] = *(const uint32_t*)(sw_lo + o);
                blo[ni][1] = *(const uint32_t*)(sw_lo + o + 16);
            }
#pragma unroll
            for (int mi = 0; mi < 2; mi++)
#pragma unroll
                for (int ni = 0; ni < 4; ni++)
                    MMA_BF16(acc[mi][ni], ahi[mi], bhi[ni]);
#pragma unroll
            for (int mi = 0; mi < 2; mi++)
#pragma unroll
                for (int ni = 0; ni < 4; ni++)
                    MMA_BF16(acc[mi][ni], ahi[mi], blo[ni]);
#pragma unroll
            for (int mi = 0; mi < 2; mi++)
#pragma unroll
                for (int ni = 0; ni < 4; ni++)
                    MMA_BF16(acc[mi][ni], alo[mi], bhi[ni]);
        }

        MBARRIVE(mb_empty[st]);

        if (tid == 0 && kb + 2 < NKH) {
            MBAR_WAIT(mb_empty[st], eph[st]); eph[st] ^= 1;
            int kg = ki * NKH + kb + 2;
            uint32_t sb = ub + 128 + st * STAGE_BYTES;
            MBEXPECT(mb_full[st], STAGE_BYTES);
            bulk_g2s(sb,              (const char*)g_Xhi + (size_t)kg * XBLK_BYTES, XBLK_BYTES, mb_full[st]);
            bulk_g2s(sb + XBLK_BYTES, (const char*)g_Xlo + (size_t)kg * XBLK_BYTES, XBLK_BYTES, mb_full[st]);
            size_t woff = (size_t)(nt * NKB + kg) * WBLK_BYTES;
            bulk_g2s(sb + 2 * XBLK_BYTES,              (const char*)g_Whi + woff, WBLK_BYTES, mb_full[st]);
            bulk_g2s(sb + 2 * XBLK_BYTES + WBLK_BYTES, (const char*)g_Wlo + woff, WBLK_BYTES, mb_full[st]);
        }
    }

    // Store partial accumulators
    float* gout = g_gates[ki];
    const int n0 = nt * 64 + ng * 32;
#pragma unroll
    for (int mi = 0; mi < 2; mi++) {
        int r0 = mp * 32 + mi * 16 + lr;
#pragma unroll
        for (int ni = 0; ni < 4; ni++) {
            int col = n0 + ni * 8 + lc * 2;
            gout[(size_t)r0 * NG + col]           = acc[mi][ni][0];
            gout[(size_t)r0 * NG + col + 1]       = acc[mi][ni][1];
            gout[(size_t)(r0 + 8) * NG + col]     = acc[mi][ni][2];
            gout[(size_t)(r0 + 8) * NG + col + 1] = acc[mi][ni][3];
        }
    }
}

// ---------------------------------------------------------------------------
// Pointwise step: combines the two K-split partials; 1024 threads/block.
// grid = B_, 1024 threads
// ---------------------------------------------------------------------------
__global__ void __launch_bounds__(1024, 1)
step_pointwise(const float* __restrict__ WUb,
               const float* __restrict__ Wa, const float* __restrict__ Wab,
               const float* __restrict__ Wx, const float* __restrict__ Wxb,
               const float* __restrict__ Amat, const float* __restrict__ tau,
               const float* __restrict__ rnn_input,
               float* __restrict__ out, int s) {
    const int b = blockIdx.x;
    const int tid = threadIdx.x;
    const int lane = tid & 31;
    const int wid = tid >> 5;

    const float* gb0 = g_gates[0] + (size_t)b * NG;
    const float* gb1 = g_gates[1] + (size_t)b * NG;
    float* outz = out + ((size_t)b * S_ + s) * ZW;

    const int n = tid;  // unit index 0..1023
    float i_ = gb0[n]          + gb1[n]          + WUb[n];
    float f_ = gb0[H_ + n]     + gb1[H_ + n]     + WUb[H_ + n];
    float g_ = gb0[2 * H_ + n] + gb1[2 * H_ + n] + WUb[2 * H_ + n];
    float o_ = gb0[3 * H_ + n] + gb1[3 * H_ + n] + WUb[3 * H_ + n];
    float c  = g_cstate[b * H_ + n];
    float cn = sigf(f_) * c + sigf(i_) * tanhfast(g_);
    float hn = sigf(o_) * tanhfast(cn);
    g_cstate[b * H_ + n] = cn;
    store_x_hilo(b, SD_ + IN_ + n, hn);
    outz[SD_ + n] = hn;

    float wa0 = Wa[n] * hn;
    float wa1 = Wa[H_ + n] * hn;
    float wx0 = Wx[n] * hn;
    float wx1 = Wx[H_ + n] * hn;

    __shared__ float red[32][4];
    unsigned mask = 0xffffffffu;
#pragma unroll
    for (int off = 16; off > 0; off >>= 1) {
        wa0 += __shfl_down_sync(mask, wa0, off);
        wa1 += __shfl_down_sync(mask, wa1, off);
        wx0 += __shfl_down_sync(mask, wx0, off);
        wx1 += __shfl_down_sync(mask, wx1, off);
    }
    if (lane == 0) {
        red[wid][0] = wa0; red[wid][1] = wa1;
        red[wid][2] = wx0; red[wid][3] = wx1;
    }
    __syncthreads();

    if (wid == 0) {
        float s0 = red[lane][0], s1 = red[lane][1];
        float s2 = red[lane][2], s3 = red[lane][3];
#pragma unroll
        for (int off = 16; off > 0; off >>= 1) {
            s0 += __shfl_down_sync(mask, s0, off);
            s1 += __shfl_down_sync(mask, s1, off);
            s2 += __shfl_down_sync(mask, s2, off);
            s3 += __shfl_down_sync(mask, s3, off);
        }
        if (lane == 0) {
            float xp0 = g_xstate[b * 2 + 0];
            float xp1 = g_xstate[b * 2 + 1];
            float t   = tau[b * S_ + s];
            float xm0 = xp0 + t * (Amat[0] * xp0 + Amat[1] * xp1);
            float xm1 = xp1 + t * (Amat[2] * xp0 + Amat[3] * xp1);
            float a0  = sigf(s0 + Wab[0]);
            float a1  = sigf(s1 + Wab[1]);
            float xt0 = s2 + Wxb[0];
            float xt1 = s3 + Wxb[1];
            float xn0 = a0 * xm0 + (1.0f - a0) * xt0;
            float xn1 = a1 * xm1 + (1.0f - a1) * xt1;
            g_xstate[b * 2 + 0] = xn0;
            g_xstate[b * 2 + 1] = xn1;
            store_x_hilo(b, 0, xn0);
            store_x_hilo(b, 1, xn1);
            outz[0] = xn0;
            outz[1] = xn1;
            float* cf = out + OUT_COEF + ((size_t)b * S_ + s) * SD_;
            cf[0] = a0;
            cf[1] = a1;
        }
    }

    if (s + 1 < S_ && tid >= 64 && tid < 64 + IN_) {
        int u = tid - 64;
        store_x_hilo(b, SD_ + u,
                     rnn_input[((size_t)b * S_ + (s + 1)) * IN_ + u]);
    }
}

// ---------------------------------------------------------------------------
// Final: z_f = outputs[:, -1, :], c_z_f = [c0[:, :2], c_final]
// ---------------------------------------------------------------------------
__global__ void final_out(const float* __restrict__ c0, float* __restrict__ out) {
    int b = blockIdx.x;
    float* zf  = out + OUT_ZF  + (size_t)b * ZW;
    float* czf = out + OUT_CZF + (size_t)b * ZW;
    const float* last = out + ((size_t)b * S_ + (S_ - 1)) * ZW;
    for (int k = threadIdx.x; k < ZW; k += 256) {
        zf[k] = last[k];
        czf[k] = (k < SD_) ? c0[b * ZW + k] : g_cstate[b * H_ + (k - SD_)];
    }
}

// ---------------------------------------------------------------------------
extern "C" void kernel_launch(void* const* d_in, const int* in_sizes, int n_in,
                              void* d_out, int out_size) {
    const float* rnn_input = (const float*)d_in[0];
    const float* z0        = (const float*)d_in[1];
    const float* c0        = (const float*)d_in[2];
    const float* tau       = (const float*)d_in[3];
    const float* A         = (const float*)d_in[4];
    const float* WU_w      = (const float*)d_in[5];
    const float* WU_b      = (const float*)d_in[6];
    const float* Wa_w      = (const float*)d_in[7];
    const float* Wa_b      = (const float*)d_in[8];
    const float* Wx_w      = (const float*)d_in[9];
    const float* Wx_b      = (const float*)d_in[10];
    float* out = (float*)d_out;

    cudaFuncSetAttribute(gates_hmma, cudaFuncAttributeMaxDynamicSharedMemorySize, SMEM_DYN);

    prep_w<<<dim3(64, NKB), 256>>>(WU_w);
    init_pack<<<B_, 128>>>(z0, c0, rnn_input);
    for (int s = 0; s < S_; s++) {
        gates_hmma<<<dim3(64, 2), 256, SMEM_DYN>>>();
        step_pointwise<<<B_, 1024>>>(WU_b, Wa_w, Wa_b, Wx_w, Wx_b, A, tau,
                                     rnn_input, out, s);
    }
    final_out<<<B_, 256>>>(c0, out);
}

// round 9
// speedup vs baseline: 2.1573x; 1.0429x over previous
#include <cuda_runtime.h>
#include <cuda_bf16.h>
#include <cstdint>
#include <cstddef>

// ---------------------------------------------------------------------------
// Problem constants
// ---------------------------------------------------------------------------
#define B_   128
#define S_   256
#define H_   1024
#define IN_  64
#define SD_  2
#define KGEMM 1088           // u(64) + h(1024); x handled as rank-2 update
#define NKB  34              // K blocks of 32
#define NKH  17              // K blocks per K-split half
#define ZW   (SD_ + H_)      // 1026
#define NG   4096

#define OUT_ZF   ((size_t)B_ * S_ * ZW)
#define OUT_CZF  (OUT_ZF + (size_t)B_ * ZW)
#define OUT_COEF (OUT_CZF + (size_t)B_ * ZW)

// Blocked layouts: rows padded to 40 bf16 (80 B) for conflict-free LDS
#define ROWB 40
#define XBLK_BYTES  (128 * ROWB * 2)          // 10240 per K-block
#define WBLK_BYTES  (64 * ROWB * 2)           // 5120 per (ntile64, kb)
#define STAGE_BYTES (2 * XBLK_BYTES + 2 * WBLK_BYTES)   // 30720
#define SMEM_DYN    (128 + 2 * STAGE_BYTES)             // 61568

// ---------------------------------------------------------------------------
// Device-global scratch
// ---------------------------------------------------------------------------
__device__ __align__(128) __nv_bfloat16 g_Xhi[(size_t)NKB * 128 * ROWB];
__device__ __align__(128) __nv_bfloat16 g_Xlo[(size_t)NKB * 128 * ROWB];
__device__ __align__(128) __nv_bfloat16 g_Whi[(size_t)64 * NKB * 64 * ROWB];
__device__ __align__(128) __nv_bfloat16 g_Wlo[(size_t)64 * NKB * 64 * ROWB];
__device__ float g_gates[2][(size_t)B_ * NG];   // two K-split partials (unit-major)
__device__ float4 g_bias4[H_];                  // per-unit (i,f,g,o) bias
__device__ float4 g_wawx4[H_];                  // {Wa0, Wa1, Wx0, Wx1} per unit
__device__ float4 g_wx2a[H_];                   // W[:,0] per unit (i,f,g,o)
__device__ float4 g_wx2b[H_];                   // W[:,1] per unit (i,f,g,o)
__device__ float g_cstate[B_ * H_];
__device__ float g_xstate[B_ * 2];

// ---------------------------------------------------------------------------
// Helpers
// ---------------------------------------------------------------------------
__device__ __forceinline__ float sigf(float x) { return 1.0f / (1.0f + __expf(-x)); }
__device__ __forceinline__ float tanhfast(float x) { return 2.0f / (1.0f + __expf(-2.0f * x)) - 1.0f; }

// X image column mapping: k 0..63 = u_t, k 64..1087 = h
__device__ __forceinline__ void store_x_hilo(int m, int k, float v) {
    int kb = k >> 5, kk = k & 31;
    size_t idx = ((size_t)kb * 128 + m) * ROWB + kk;
    __nv_bfloat16 hi = __float2bfloat16_rn(v);
    float r = v - __bfloat162float(hi);
    g_Xhi[idx] = hi;
    g_Xlo[idx] = __float2bfloat16_rn(r);
}

__device__ __forceinline__ uint32_t smem_u32(const void* p) {
    uint32_t a;
    asm("{ .reg .u64 t; cvta.to.shared.u64 t, %1; cvt.u32.u64 %0, t; }" : "=r"(a) : "l"(p));
    return a;
}

#define MBINIT(a, c)  asm volatile("mbarrier.init.shared.b64 [%0], %1;" :: "r"(a), "r"(c) : "memory")
#define MBEXPECT(a,b) asm volatile("mbarrier.arrive.expect_tx.shared.b64 _, [%0], %1;" :: "r"(a), "r"(b) : "memory")
#define MBARRIVE(a)   asm volatile("mbarrier.arrive.shared.b64 _, [%0];" :: "r"(a) : "memory")

#define MBAR_WAIT(mbar, ph) do {                                             \
    uint32_t _m = (mbar); uint32_t _p = (ph); uint32_t _ok;                  \
    asm volatile("{\n\t.reg .pred p;\n\t"                                    \
        "mbarrier.try_wait.parity.acquire.cta.shared::cta.b64 p, [%1], %2;\n\t" \
        "selp.b32 %0, 1, 0, p;\n\t}" : "=r"(_ok) : "r"(_m), "r"(_p) : "memory"); \
    while (!_ok) {                                                           \
        asm volatile("{\n\t.reg .pred p;\n\t"                                \
            "mbarrier.try_wait.parity.acquire.cta.shared::cta.b64 p, [%1], %2, 0x989680;\n\t" \
            "selp.b32 %0, 1, 0, p;\n\t}" : "=r"(_ok) : "r"(_m), "r"(_p) : "memory"); \
    }                                                                        \
} while (0)

__device__ __forceinline__ void bulk_g2s(uint32_t dst, const void* src, uint32_t bytes, uint32_t mbar) {
    asm volatile("cp.async.bulk.shared::cluster.global.mbarrier::complete_tx::bytes [%0], [%1], %2, [%3];"
                 :: "r"(dst), "l"(src), "r"(bytes), "r"(mbar) : "memory");
}

#define MMA_BF16(acc, a, b)                                                  \
    asm volatile("mma.sync.aligned.m16n8k16.row.col.f32.bf16.bf16.f32 "      \
                 "{%0,%1,%2,%3},{%4,%5,%6,%7},{%8,%9},{%0,%1,%2,%3};"        \
                 : "+f"((acc)[0]), "+f"((acc)[1]), "+f"((acc)[2]), "+f"((acc)[3]) \
                 : "r"((a)[0]), "r"((a)[1]), "r"((a)[2]), "r"((a)[3]),       \
                   "r"((b)[0]), "r"((b)[1]))

// Unit-major permutation: GEMM column j -> W row (j&3)*H + (j>>2)
__device__ __forceinline__ int orig_row(int j) {
    return (j & 3) * H_ + (j >> 2);
}

// ---------------------------------------------------------------------------
// prep_w: W [4096][1090] fp32 -> blocked, unit-major, K=u|h split-bf16 images
// grid (64 ntiles, 34 kb), 256 threads
// ---------------------------------------------------------------------------
__global__ void prep_w(const float* __restrict__ W) {
    int nt = blockIdx.x, kb = blockIdx.y;
    size_t base = ((size_t)(nt * NKB + kb)) * 64 * ROWB;
    for (int i = threadIdx.x; i < 64 * ROWB; i += 256) {
        int nloc = i / ROWB, kk = i % ROWB;
        int j = nt * 64 + nloc;
        int n = orig_row(j);
        int k = kb * 32 + kk;          // GEMM k; original col = k + SD_
        float v = (kk < 32 && k < KGEMM) ? W[(size_t)n * (SD_ + IN_ + H_) + (k + SD_)] : 0.0f;
        __nv_bfloat16 hi = __float2bfloat16_rn(v);
        float r = v - __bfloat162float(hi);
        g_Whi[base + i] = hi;
        g_Wlo[base + i] = __float2bfloat16_rn(r);
    }
}

// ---------------------------------------------------------------------------
// prep_small: pack bias / Wa / Wx / W x-columns as per-unit float4
// grid 4, 256 threads
// ---------------------------------------------------------------------------
__global__ void prep_small(const float* __restrict__ W, const float* __restrict__ WUb,
                           const float* __restrict__ Wa, const float* __restrict__ Wx) {
    int u = blockIdx.x * 256 + threadIdx.x;
    if (u >= H_) return;
    const int KW = SD_ + IN_ + H_;
    g_bias4[u] = make_float4(WUb[u], WUb[H_ + u], WUb[2 * H_ + u], WUb[3 * H_ + u]);
    g_wawx4[u] = make_float4(Wa[u], Wa[H_ + u], Wx[u], Wx[H_ + u]);
    g_wx2a[u] = make_float4(W[(size_t)u * KW], W[(size_t)(H_ + u) * KW],
                            W[(size_t)(2 * H_ + u) * KW], W[(size_t)(3 * H_ + u) * KW]);
    g_wx2b[u] = make_float4(W[(size_t)u * KW + 1], W[(size_t)(H_ + u) * KW + 1],
                            W[(size_t)(2 * H_ + u) * KW + 1], W[(size_t)(3 * H_ + u) * KW + 1]);
}

// ---------------------------------------------------------------------------
// init_pack: X image for step 0 ([u_0 | h_0]), states
// grid B_, 128 threads
// ---------------------------------------------------------------------------
__global__ void init_pack(const float* __restrict__ z0, const float* __restrict__ c0,
                          const float* __restrict__ rnn_input) {
    int b = blockIdx.x;
    for (int i = threadIdx.x; i < NKB * ROWB; i += 128) {
        int kb = i / ROWB, kk = i % ROWB;
        int k = kb * 32 + kk;
        float v = 0.0f;
        if (kk < 32) {
            if (k < IN_)            v = rnn_input[((size_t)b * S_) * IN_ + k];
            else if (k < KGEMM)     v = z0[b * ZW + SD_ + (k - IN_)];
        }
        size_t idx = ((size_t)kb * 128 + b) * ROWB + kk;
        __nv_bfloat16 hi = __float2bfloat16_rn(v);
        float r = v - __bfloat162float(hi);
        g_Xhi[idx] = hi;
        g_Xlo[idx] = __float2bfloat16_rn(r);
    }
    for (int n = threadIdx.x; n < H_; n += 128)
        g_cstate[b * H_ + n] = c0[b * ZW + SD_ + n];
    if (threadIdx.x < 2) g_xstate[b * 2 + threadIdx.x] = z0[b * ZW + threadIdx.x];
}

// ---------------------------------------------------------------------------
// gates_hmma: partial C = Xsplit @ Wsplit^T over one K half (split-bf16 x3)
// grid = (64 ntiles, 2 ksplit), 256 threads = 8 warps (2/SMSP).
// ---------------------------------------------------------------------------
__global__ void __launch_bounds__(256, 1)
gates_hmma() {
    extern __shared__ char dsm[];
    uint32_t ub = smem_u32(dsm);
    const int nt  = blockIdx.x;
    const int ki  = blockIdx.y;          // K-split half
    const int tid = threadIdx.x;
    const int wid = tid >> 5;
    const int lane = tid & 31;
    const int lr = lane >> 2, lc = lane & 3;
    const int mp = wid & 3;              // M position (32 rows)
    const int ng = wid >> 2;             // N group (32 cols)

    uint32_t mb_full[2]  = {ub + 0,  ub + 8};
    uint32_t mb_empty[2] = {ub + 16, ub + 24};
    char* tiles = dsm + 128;

    if (tid == 0) {
        MBINIT(mb_full[0], 1);  MBINIT(mb_full[1], 1);
        MBINIT(mb_empty[0], 256); MBINIT(mb_empty[1], 256);
        asm volatile("fence.proxy.async.shared::cta;" ::: "memory");
    }
    __syncthreads();

    if (tid == 0) {
#pragma unroll
        for (int kb = 0; kb < 2; kb++) {
            int kg = ki * NKH + kb;
            uint32_t sb = ub + 128 + kb * STAGE_BYTES;
            MBEXPECT(mb_full[kb], STAGE_BYTES);
            bulk_g2s(sb,              (const char*)g_Xhi + (size_t)kg * XBLK_BYTES, XBLK_BYTES, mb_full[kb]);
            bulk_g2s(sb + XBLK_BYTES, (const char*)g_Xlo + (size_t)kg * XBLK_BYTES, XBLK_BYTES, mb_full[kb]);
            size_t woff = (size_t)(nt * NKB + kg) * WBLK_BYTES;
            bulk_g2s(sb + 2 * XBLK_BYTES,              (const char*)g_Whi + woff, WBLK_BYTES, mb_full[kb]);
            bulk_g2s(sb + 2 * XBLK_BYTES + WBLK_BYTES, (const char*)g_Wlo + woff, WBLK_BYTES, mb_full[kb]);
        }
    }

    float acc[2][4][4];
#pragma unroll
    for (int mi = 0; mi < 2; mi++)
#pragma unroll
        for (int ni = 0; ni < 4; ni++)
#pragma unroll
            for (int e = 0; e < 4; e++) acc[mi][ni][e] = 0.0f;

    int fph[2] = {0, 0}, eph[2] = {0, 0};

    for (int kb = 0; kb < NKH; kb++) {
        int st = kb & 1;
        char* sx_hi = tiles + st * STAGE_BYTES;
        char* sx_lo = sx_hi + XBLK_BYTES;
        char* sw_hi = sx_hi + 2 * XBLK_BYTES;
        char* sw_lo = sw_hi + WBLK_BYTES;

        MBAR_WAIT(mb_full[st], fph[st]); fph[st] ^= 1;

#pragma unroll
        for (int ks = 0; ks < 2; ks++) {
            uint32_t ahi[2][4], alo[2][4], bhi[4][2], blo[4][2];
#pragma unroll
            for (int mi = 0; mi < 2; mi++) {
                int o = (mp * 32 + mi * 16 + lr) * 80 + ks * 32 + lc * 4;
                ahi[mi][0] = *(const uint32_t*)(sx_hi + o);
                ahi[mi][1] = *(const uint32_t*)(sx_hi + o + 640);
                ahi[mi][2] = *(const uint32_t*)(sx_hi + o + 16);
                ahi[mi][3] = *(const uint32_t*)(sx_hi + o + 656);
                alo[mi][0] = *(const uint32_t*)(sx_lo + o);
                alo[mi][1] = *(const uint32_t*)(sx_lo + o + 640);
                alo[mi][2] = *(const uint32_t*)(sx_lo + o + 16);
                alo[mi][3] = *(const uint32_t*)(sx_lo + o + 656);
            }
#pragma unroll
            for (int ni = 0; ni < 4; ni++) {
                int o = (ng * 32 + ni * 8 + lr) * 80 + ks * 32 + lc * 4;
                bhi[ni][0] = *(const uint32_t*)(sw_hi + o);
                bhi[ni][1] = *(const uint32_t*)(sw_hi + o + 16);
                blo[ni][0] = *(const uint32_t*)(sw_lo + o);
                blo[ni][1] = *(const uint32_t*)(sw_lo + o + 16);
            }
#pragma unroll
            for (int mi = 0; mi < 2; mi++)
#pragma unroll
                for (int ni = 0; ni < 4; ni++)
                    MMA_BF16(acc[mi][ni], ahi[mi], bhi[ni]);
#pragma unroll
            for (int mi = 0; mi < 2; mi++)
#pragma unroll
                for (int ni = 0; ni < 4; ni++)
                    MMA_BF16(acc[mi][ni], ahi[mi], blo[ni]);
#pragma unroll
            for (int mi = 0; mi < 2; mi++)
#pragma unroll
                for (int ni = 0; ni < 4; ni++)
                    MMA_BF16(acc[mi][ni], alo[mi], bhi[ni]);
        }

        MBARRIVE(mb_empty[st]);

        if (tid == 0 && kb + 2 < NKH) {
            MBAR_WAIT(mb_empty[st], eph[st]); eph[st] ^= 1;
            int kg = ki * NKH + kb + 2;
            uint32_t sb = ub + 128 + st * STAGE_BYTES;
            MBEXPECT(mb_full[st], STAGE_BYTES);
            bulk_g2s(sb,              (const char*)g_Xhi + (size_t)kg * XBLK_BYTES, XBLK_BYTES, mb_full[st]);
            bulk_g2s(sb + XBLK_BYTES, (const char*)g_Xlo + (size_t)kg * XBLK_BYTES, XBLK_BYTES, mb_full[st]);
            size_t woff = (size_t)(nt * NKB + kg) * WBLK_BYTES;
            bulk_g2s(sb + 2 * XBLK_BYTES,              (const char*)g_Whi + woff, WBLK_BYTES, mb_full[st]);
            bulk_g2s(sb + 2 * XBLK_BYTES + WBLK_BYTES, (const char*)g_Wlo + woff, WBLK_BYTES, mb_full[st]);
        }
    }

    // Store partial accumulators
    float* gout = g_gates[ki];
    const int n0 = nt * 64 + ng * 32;
#pragma unroll
    for (int mi = 0; mi < 2; mi++) {
        int r0 = mp * 32 + mi * 16 + lr;
#pragma unroll
        for (int ni = 0; ni < 4; ni++) {
            int col = n0 + ni * 8 + lc * 2;
            gout[(size_t)r0 * NG + col]           = acc[mi][ni][0];
            gout[(size_t)r0 * NG + col + 1]       = acc[mi][ni][1];
            gout[(size_t)(r0 + 8) * NG + col]     = acc[mi][ni][2];
            gout[(size_t)(r0 + 8) * NG + col + 1] = acc[mi][ni][3];
        }
    }
}

// ---------------------------------------------------------------------------
// Pointwise step: float4 unit-major gate reads + rank-2 x contribution +
// prefetched tail scalars. grid = B_, 1024 threads.
// ---------------------------------------------------------------------------
__global__ void __launch_bounds__(1024, 1)
step_pointwise(const float* __restrict__ Wab, const float* __restrict__ Wxb,
               const float* __restrict__ Amat, const float* __restrict__ tau,
               const float* __restrict__ rnn_input,
               float* __restrict__ out, int s) {
    const int b = blockIdx.x;
    const int tid = threadIdx.x;
    const int lane = tid & 31;
    const int wid = tid >> 5;

    __shared__ float sPre[12];
    // Prefetch tail scalars in parallel with the body
    if (tid < 9) {
        float v;
        if (tid == 0)      v = tau[b * S_ + s];
        else if (tid < 5)  v = Amat[tid - 1];
        else if (tid < 7)  v = Wab[tid - 5];
        else               v = Wxb[tid - 7];
        sPre[tid] = v;
    }

    const float x0 = g_xstate[b * 2 + 0];
    const float x1 = g_xstate[b * 2 + 1];

    const float4* gb0 = (const float4*)(g_gates[0] + (size_t)b * NG);
    const float4* gb1 = (const float4*)(g_gates[1] + (size_t)b * NG);
    float* outz = out + ((size_t)b * S_ + s) * ZW;

    const int n = tid;  // unit index 0..1023
    float4 p0 = gb0[n];
    float4 p1 = gb1[n];
    float4 bi = g_bias4[n];
    float4 xa = g_wx2a[n];
    float4 xb = g_wx2b[n];
    float i_ = p0.x + p1.x + bi.x + x0 * xa.x + x1 * xb.x;
    float f_ = p0.y + p1.y + bi.y + x0 * xa.y + x1 * xb.y;
    float g_ = p0.z + p1.z + bi.z + x0 * xa.z + x1 * xb.z;
    float o_ = p0.w + p1.w + bi.w + x0 * xa.w + x1 * xb.w;
    float c  = g_cstate[b * H_ + n];
    float cn = sigf(f_) * c + sigf(i_) * tanhfast(g_);
    float hn = sigf(o_) * tanhfast(cn);
    g_cstate[b * H_ + n] = cn;
    store_x_hilo(b, IN_ + n, hn);
    outz[SD_ + n] = hn;

    float4 ww = g_wawx4[n];
    float wa0 = ww.x * hn;
    float wa1 = ww.y * hn;
    float wx0 = ww.z * hn;
    float wx1 = ww.w * hn;

    __shared__ float red[32][4];
    unsigned mask = 0xffffffffu;
#pragma unroll
    for (int off = 16; off > 0; off >>= 1) {
        wa0 += __shfl_down_sync(mask, wa0, off);
        wa1 += __shfl_down_sync(mask, wa1, off);
        wx0 += __shfl_down_sync(mask, wx0, off);
        wx1 += __shfl_down_sync(mask, wx1, off);
    }
    if (lane == 0) {
        red[wid][0] = wa0; red[wid][1] = wa1;
        red[wid][2] = wx0; red[wid][3] = wx1;
    }
    __syncthreads();

    if (wid == 0) {
        float s0 = red[lane][0], s1 = red[lane][1];
        float s2 = red[lane][2], s3 = red[lane][3];
#pragma unroll
        for (int off = 16; off > 0; off >>= 1) {
            s0 += __shfl_down_sync(mask, s0, off);
            s1 += __shfl_down_sync(mask, s1, off);
            s2 += __shfl_down_sync(mask, s2, off);
            s3 += __shfl_down_sync(mask, s3, off);
        }
        if (lane == 0) {
            float t   = sPre[0];
            float xm0 = x0 + t * (sPre[1] * x0 + sPre[2] * x1);
            float xm1 = x1 + t * (sPre[3] * x0 + sPre[4] * x1);
            float a0  = sigf(s0 + sPre[5]);
            float a1  = sigf(s1 + sPre[6]);
            float xt0 = s2 + sPre[7];
            float xt1 = s3 + sPre[8];
            float xn0 = a0 * xm0 + (1.0f - a0) * xt0;
            float xn1 = a1 * xm1 + (1.0f - a1) * xt1;
            g_xstate[b * 2 + 0] = xn0;
            g_xstate[b * 2 + 1] = xn1;
            outz[0] = xn0;
            outz[1] = xn1;
            float* cf = out + OUT_COEF + ((size_t)b * S_ + s) * SD_;
            cf[0] = a0;
            cf[1] = a1;
        }
    }

    if (s + 1 < S_ && tid >= 128 && tid < 128 + IN_) {
        int u = tid - 128;
        store_x_hilo(b, u, rnn_input[((size_t)b * S_ + (s + 1)) * IN_ + u]);
    }
}

// ---------------------------------------------------------------------------
// Final: z_f = outputs[:, -1, :], c_z_f = [c0[:, :2], c_final]
// ---------------------------------------------------------------------------
__global__ void final_out(const float* __restrict__ c0, float* __restrict__ out) {
    int b = blockIdx.x;
    float* zf  = out + OUT_ZF  + (size_t)b * ZW;
    float* czf = out + OUT_CZF + (size_t)b * ZW;
    const float* last = out + ((size_t)b * S_ + (S_ - 1)) * ZW;
    for (int k = threadIdx.x; k < ZW; k += 256) {
        zf[k] = last[k];
        czf[k] = (k < SD_) ? c0[b * ZW + k] : g_cstate[b * H_ + (k - SD_)];
    }
}

// ---------------------------------------------------------------------------
extern "C" void kernel_launch(void* const* d_in, const int* in_sizes, int n_in,
                              void* d_out, int out_size) {
    const float* rnn_input = (const float*)d_in[0];
    const float* z0        = (const float*)d_in[1];
    const float* c0        = (const float*)d_in[2];
    const float* tau       = (const float*)d_in[3];
    const float* A         = (const float*)d_in[4];
    const float* WU_w      = (const float*)d_in[5];
    const float* WU_b      = (const float*)d_in[6];
    const float* Wa_w      = (const float*)d_in[7];
    const float* Wa_b      = (const float*)d_in[8];
    const float* Wx_w      = (const float*)d_in[9];
    const float* Wx_b      = (const float*)d_in[10];
    float* out = (float*)d_out;

    cudaFuncSetAttribute(gates_hmma, cudaFuncAttributeMaxDynamicSharedMemorySize, SMEM_DYN);

    prep_w<<<dim3(64, NKB), 256>>>(WU_w);
    prep_small<<<4, 256>>>(WU_w, WU_b, Wa_w, Wx_w);
    init_pack<<<B_, 128>>>(z0, c0, rnn_input);
    for (int s = 0; s < S_; s++) {
        gates_hmma<<<dim3(64, 2), 256, SMEM_DYN>>>();
        step_pointwise<<<B_, 1024>>>(Wa_b, Wx_b, A, tau, rnn_input, out, s);
    }
    final_out<<<B_, 256>>>(c0, out);
}

// round 10
// speedup vs baseline: 2.5390x; 1.1769x over previous
#include <cuda_runtime.h>
#include <cuda_bf16.h>
#include <cstdint>
#include <cstddef>

// ---------------------------------------------------------------------------
// Problem constants
// ---------------------------------------------------------------------------
#define B_   128
#define S_   256
#define H_   1024
#define IN_  64
#define SD_  2
#define KGEMM 1088           // u(64) + h(1024); x handled as rank-2 update
#define NKB  34              // K blocks of 32
#define NKH  17              // K blocks per K-split half
#define ZW   (SD_ + H_)      // 1026
#define NG   4096

#define OUT_ZF   ((size_t)B_ * S_ * ZW)
#define OUT_CZF  (OUT_ZF + (size_t)B_ * ZW)
#define OUT_COEF (OUT_CZF + (size_t)B_ * ZW)

// Blocked layouts: rows padded to 40 bf16 (80 B) for conflict-free LDS/LDSM
#define ROWB 40
#define XBLK_BYTES  (128 * ROWB * 2)          // 10240 per K-block
#define WBLK_BYTES  (64 * ROWB * 2)           // 5120 per (ntile64, kb)
#define STAGE_BYTES (2 * XBLK_BYTES + 2 * WBLK_BYTES)   // 30720
#define SMEM_DYN    (128 + 2 * STAGE_BYTES)             // 61568

// ---------------------------------------------------------------------------
// Device-global scratch
// ---------------------------------------------------------------------------
__device__ __align__(128) __nv_bfloat16 g_Xhi[(size_t)NKB * 128 * ROWB];
__device__ __align__(128) __nv_bfloat16 g_Xlo[(size_t)NKB * 128 * ROWB];
__device__ __align__(128) __nv_bfloat16 g_Whi[(size_t)64 * NKB * 64 * ROWB];
__device__ __align__(128) __nv_bfloat16 g_Wlo[(size_t)64 * NKB * 64 * ROWB];
__device__ float g_gates[2][(size_t)B_ * NG];   // two K-split partials (unit-major)
__device__ float4 g_bias4[H_];                  // per-unit (i,f,g,o) bias
__device__ float4 g_wawx4[H_];                  // {Wa0, Wa1, Wx0, Wx1} per unit
__device__ float4 g_wx2a[H_];                   // W[:,0] per unit (i,f,g,o)
__device__ float4 g_wx2b[H_];                   // W[:,1] per unit (i,f,g,o)
__device__ float g_cstate[B_ * H_];
__device__ float g_xstate[B_ * 2];

// ---------------------------------------------------------------------------
// Helpers
// ---------------------------------------------------------------------------
__device__ __forceinline__ float sigf(float x) { return 1.0f / (1.0f + __expf(-x)); }
__device__ __forceinline__ float tanhfast(float x) { return 2.0f / (1.0f + __expf(-2.0f * x)) - 1.0f; }

// X image column mapping: k 0..63 = u_t, k 64..1087 = h
__device__ __forceinline__ void store_x_hilo(int m, int k, float v) {
    int kb = k >> 5, kk = k & 31;
    size_t idx = ((size_t)kb * 128 + m) * ROWB + kk;
    __nv_bfloat16 hi = __float2bfloat16_rn(v);
    float r = v - __bfloat162float(hi);
    g_Xhi[idx] = hi;
    g_Xlo[idx] = __float2bfloat16_rn(r);
}

__device__ __forceinline__ uint32_t smem_u32(const void* p) {
    uint32_t a;
    asm("{ .reg .u64 t; cvta.to.shared.u64 t, %1; cvt.u32.u64 %0, t; }" : "=r"(a) : "l"(p));
    return a;
}

#define MBINIT(a, c)  asm volatile("mbarrier.init.shared.b64 [%0], %1;" :: "r"(a), "r"(c) : "memory")
#define MBEXPECT(a,b) asm volatile("mbarrier.arrive.expect_tx.shared.b64 _, [%0], %1;" :: "r"(a), "r"(b) : "memory")
#define MBARRIVE(a)   asm volatile("mbarrier.arrive.shared.b64 _, [%0];" :: "r"(a) : "memory")

#define MBAR_WAIT(mbar, ph) do {                                             \
    uint32_t _m = (mbar); uint32_t _p = (ph); uint32_t _ok;                  \
    asm volatile("{\n\t.reg .pred p;\n\t"                                    \
        "mbarrier.try_wait.parity.acquire.cta.shared::cta.b64 p, [%1], %2;\n\t" \
        "selp.b32 %0, 1, 0, p;\n\t}" : "=r"(_ok) : "r"(_m), "r"(_p) : "memory"); \
    while (!_ok) {                                                           \
        asm volatile("{\n\t.reg .pred p;\n\t"                                \
            "mbarrier.try_wait.parity.acquire.cta.shared::cta.b64 p, [%1], %2, 0x989680;\n\t" \
            "selp.b32 %0, 1, 0, p;\n\t}" : "=r"(_ok) : "r"(_m), "r"(_p) : "memory"); \
    }                                                                        \
} while (0)

__device__ __forceinline__ void bulk_g2s(uint32_t dst, const void* src, uint32_t bytes, uint32_t mbar) {
    asm volatile("cp.async.bulk.shared::cluster.global.mbarrier::complete_tx::bytes [%0], [%1], %2, [%3];"
                 :: "r"(dst), "l"(src), "r"(bytes), "r"(mbar) : "memory");
}

#define MMA_BF16(acc, a, b)                                                  \
    asm volatile("mma.sync.aligned.m16n8k16.row.col.f32.bf16.bf16.f32 "      \
                 "{%0,%1,%2,%3},{%4,%5,%6,%7},{%8,%9},{%0,%1,%2,%3};"        \
                 : "+f"((acc)[0]), "+f"((acc)[1]), "+f"((acc)[2]), "+f"((acc)[3]) \
                 : "r"((a)[0]), "r"((a)[1]), "r"((a)[2]), "r"((a)[3]),       \
                   "r"((b)[0]), "r"((b)[1]))

#define LDSM_X4(r0, r1, r2, r3, addr)                                        \
    asm volatile("ldmatrix.sync.aligned.m8n8.x4.shared.b16 {%0,%1,%2,%3}, [%4];" \
                 : "=r"(r0), "=r"(r1), "=r"(r2), "=r"(r3) : "r"(addr))

// Unit-major permutation: GEMM column j -> W row (j&3)*H + (j>>2)
__device__ __forceinline__ int orig_row(int j) {
    return (j & 3) * H_ + (j >> 2);
}

// ---------------------------------------------------------------------------
// prep_w: W [4096][1090] fp32 -> blocked, unit-major, K=u|h split-bf16 images
// grid (64 ntiles, 34 kb), 256 threads
// ---------------------------------------------------------------------------
__global__ void prep_w(const float* __restrict__ W) {
    int nt = blockIdx.x, kb = blockIdx.y;
    size_t base = ((size_t)(nt * NKB + kb)) * 64 * ROWB;
    for (int i = threadIdx.x; i < 64 * ROWB; i += 256) {
        int nloc = i / ROWB, kk = i % ROWB;
        int j = nt * 64 + nloc;
        int n = orig_row(j);
        int k = kb * 32 + kk;          // GEMM k; original col = k + SD_
        float v = (kk < 32 && k < KGEMM) ? W[(size_t)n * (SD_ + IN_ + H_) + (k + SD_)] : 0.0f;
        __nv_bfloat16 hi = __float2bfloat16_rn(v);
        float r = v - __bfloat162float(hi);
        g_Whi[base + i] = hi;
        g_Wlo[base + i] = __float2bfloat16_rn(r);
    }
}

// ---------------------------------------------------------------------------
// prep_small: pack bias / Wa / Wx / W x-columns as per-unit float4
// grid 4, 256 threads
// ---------------------------------------------------------------------------
__global__ void prep_small(const float* __restrict__ W, const float* __restrict__ WUb,
                           const float* __restrict__ Wa, const float* __restrict__ Wx) {
    int u = blockIdx.x * 256 + threadIdx.x;
    if (u >= H_) return;
    const int KW = SD_ + IN_ + H_;
    g_bias4[u] = make_float4(WUb[u], WUb[H_ + u], WUb[2 * H_ + u], WUb[3 * H_ + u]);
    g_wawx4[u] = make_float4(Wa[u], Wa[H_ + u], Wx[u], Wx[H_ + u]);
    g_wx2a[u] = make_float4(W[(size_t)u * KW], W[(size_t)(H_ + u) * KW],
                            W[(size_t)(2 * H_ + u) * KW], W[(size_t)(3 * H_ + u) * KW]);
    g_wx2b[u] = make_float4(W[(size_t)u * KW + 1], W[(size_t)(H_ + u) * KW + 1],
                            W[(size_t)(2 * H_ + u) * KW + 1], W[(size_t)(3 * H_ + u) * KW + 1]);
}

// ---------------------------------------------------------------------------
// init_pack: X image for step 0 ([u_0 | h_0]), states
// grid B_, 128 threads
// ---------------------------------------------------------------------------
__global__ void init_pack(const float* __restrict__ z0, const float* __restrict__ c0,
                          const float* __restrict__ rnn_input) {
    int b = blockIdx.x;
    for (int i = threadIdx.x; i < NKB * ROWB; i += 128) {
        int kb = i / ROWB, kk = i % ROWB;
        int k = kb * 32 + kk;
        float v = 0.0f;
        if (kk < 32) {
            if (k < IN_)            v = rnn_input[((size_t)b * S_) * IN_ + k];
            else if (k < KGEMM)     v = z0[b * ZW + SD_ + (k - IN_)];
        }
        size_t idx = ((size_t)kb * 128 + b) * ROWB + kk;
        __nv_bfloat16 hi = __float2bfloat16_rn(v);
        float r = v - __bfloat162float(hi);
        g_Xhi[idx] = hi;
        g_Xlo[idx] = __float2bfloat16_rn(r);
    }
    for (int n = threadIdx.x; n < H_; n += 128)
        g_cstate[b * H_ + n] = c0[b * ZW + SD_ + n];
    if (threadIdx.x < 2) g_xstate[b * 2 + threadIdx.x] = z0[b * ZW + threadIdx.x];
}

// ---------------------------------------------------------------------------
// gates_hmma: partial C = Xsplit @ Wsplit^T over one K half (split-bf16 x3)
// grid = (64 ntiles, 2 ksplit), 256 threads = 8 warps (2/SMSP).
// Fragment loads via ldmatrix.x4 (8 LDSM vs 32 LDS per ks iteration).
// ---------------------------------------------------------------------------
__global__ void __launch_bounds__(256, 1)
gates_hmma() {
    extern __shared__ char dsm[];
    uint32_t ub = smem_u32(dsm);
    const int nt  = blockIdx.x;
    const int ki  = blockIdx.y;          // K-split half
    const int tid = threadIdx.x;
    const int wid = tid >> 5;
    const int lane = tid & 31;
    const int lr = lane >> 2, lc = lane & 3;
    const int mp = wid & 3;              // M position (32 rows)
    const int ng = wid >> 2;             // N group (32 cols)

    uint32_t mb_full[2]  = {ub + 0,  ub + 8};
    uint32_t mb_empty[2] = {ub + 16, ub + 24};
    const uint32_t tiles_u = ub + 128;

    // ldmatrix per-lane byte offsets (within a tile image)
    // A (per mi): matrix idx = lane>>3: m0 rows+0 k0, m1 rows+8 k0, m2 rows+0 k8, m3 rows+8 k8
    const int a_row = mp * 32 + (lane & 7) + ((lane >> 3) & 1) * 8;
    const uint32_t a_off0 = (uint32_t)(a_row * 80 + (lane >> 4) * 16);           // mi=0
    const uint32_t a_off1 = a_off0 + 16 * 80;                                    // mi=1
    // B (per group g of 2 ni): m0 (ni=g*2,k0), m1 (ni=g*2,k8), m2 (ni=g*2+1,k0), m3 (..,k8)
    const int b_row0 = ng * 32 + (lane >> 4) * 8 + (lane & 7);                   // g=0
    const uint32_t b_off0 = (uint32_t)(b_row0 * 80 + ((lane >> 3) & 1) * 16);
    const uint32_t b_off1 = b_off0 + 16 * 80;                                    // g=1

    if (tid == 0) {
        MBINIT(mb_full[0], 1);  MBINIT(mb_full[1], 1);
        MBINIT(mb_empty[0], 256); MBINIT(mb_empty[1], 256);
        asm volatile("fence.proxy.async.shared::cta;" ::: "memory");
    }
    __syncthreads();

    if (tid == 0) {
#pragma unroll
        for (int kb = 0; kb < 2; kb++) {
            int kg = ki * NKH + kb;
            uint32_t sb = tiles_u + kb * STAGE_BYTES;
            MBEXPECT(mb_full[kb], STAGE_BYTES);
            bulk_g2s(sb,              (const char*)g_Xhi + (size_t)kg * XBLK_BYTES, XBLK_BYTES, mb_full[kb]);
            bulk_g2s(sb + XBLK_BYTES, (const char*)g_Xlo + (size_t)kg * XBLK_BYTES, XBLK_BYTES, mb_full[kb]);
            size_t woff = (size_t)(nt * NKB + kg) * WBLK_BYTES;
            bulk_g2s(sb + 2 * XBLK_BYTES,              (const char*)g_Whi + woff, WBLK_BYTES, mb_full[kb]);
            bulk_g2s(sb + 2 * XBLK_BYTES + WBLK_BYTES, (const char*)g_Wlo + woff, WBLK_BYTES, mb_full[kb]);
        }
    }

    float acc[2][4][4];
#pragma unroll
    for (int mi = 0; mi < 2; mi++)
#pragma unroll
        for (int ni = 0; ni < 4; ni++)
#pragma unroll
            for (int e = 0; e < 4; e++) acc[mi][ni][e] = 0.0f;

    int fph[2] = {0, 0}, eph[2] = {0, 0};

    for (int kb = 0; kb < NKH; kb++) {
        int st = kb & 1;
        uint32_t sx_hi = tiles_u + st * STAGE_BYTES;
        uint32_t sx_lo = sx_hi + XBLK_BYTES;
        uint32_t sw_hi = sx_hi + 2 * XBLK_BYTES;
        uint32_t sw_lo = sw_hi + WBLK_BYTES;

        MBAR_WAIT(mb_full[st], fph[st]); fph[st] ^= 1;

#pragma unroll
        for (int ks = 0; ks < 2; ks++) {
            const uint32_t ko = ks * 32;
            uint32_t ahi[2][4], alo[2][4], bhi[4][2], blo[4][2];
            LDSM_X4(ahi[0][0], ahi[0][1], ahi[0][2], ahi[0][3], sx_hi + a_off0 + ko);
            LDSM_X4(ahi[1][0], ahi[1][1], ahi[1][2], ahi[1][3], sx_hi + a_off1 + ko);
            LDSM_X4(bhi[0][0], bhi[0][1], bhi[1][0], bhi[1][1], sw_hi + b_off0 + ko);
            LDSM_X4(bhi[2][0], bhi[2][1], bhi[3][0], bhi[3][1], sw_hi + b_off1 + ko);
            LDSM_X4(alo[0][0], alo[0][1], alo[0][2], alo[0][3], sx_lo + a_off0 + ko);
            LDSM_X4(alo[1][0], alo[1][1], alo[1][2], alo[1][3], sx_lo + a_off1 + ko);
            LDSM_X4(blo[0][0], blo[0][1], blo[1][0], blo[1][1], sw_lo + b_off0 + ko);
            LDSM_X4(blo[2][0], blo[2][1], blo[3][0], blo[3][1], sw_lo + b_off1 + ko);
#pragma unroll
            for (int mi = 0; mi < 2; mi++)
#pragma unroll
                for (int ni = 0; ni < 4; ni++)
                    MMA_BF16(acc[mi][ni], ahi[mi], bhi[ni]);
#pragma unroll
            for (int mi = 0; mi < 2; mi++)
#pragma unroll
                for (int ni = 0; ni < 4; ni++)
                    MMA_BF16(acc[mi][ni], ahi[mi], blo[ni]);
#pragma unroll
            for (int mi = 0; mi < 2; mi++)
#pragma unroll
                for (int ni = 0; ni < 4; ni++)
                    MMA_BF16(acc[mi][ni], alo[mi], bhi[ni]);
        }

        MBARRIVE(mb_empty[st]);

        if (tid == 0 && kb + 2 < NKH) {
            MBAR_WAIT(mb_empty[st], eph[st]); eph[st] ^= 1;
            int kg = ki * NKH + kb + 2;
            uint32_t sb = tiles_u + st * STAGE_BYTES;
            MBEXPECT(mb_full[st], STAGE_BYTES);
            bulk_g2s(sb,              (const char*)g_Xhi + (size_t)kg * XBLK_BYTES, XBLK_BYTES, mb_full[st]);
            bulk_g2s(sb + XBLK_BYTES, (const char*)g_Xlo + (size_t)kg * XBLK_BYTES, XBLK_BYTES, mb_full[st]);
            size_t woff = (size_t)(nt * NKB + kg) * WBLK_BYTES;
            bulk_g2s(sb + 2 * XBLK_BYTES,              (const char*)g_Whi + woff, WBLK_BYTES, mb_full[st]);
            bulk_g2s(sb + 2 * XBLK_BYTES + WBLK_BYTES, (const char*)g_Wlo + woff, WBLK_BYTES, mb_full[st]);
        }
    }

    // Store partial accumulators
    float* gout = g_gates[ki];
    const int n0 = nt * 64 + ng * 32;
#pragma unroll
    for (int mi = 0; mi < 2; mi++) {
        int r0 = mp * 32 + mi * 16 + lr;
#pragma unroll
        for (int ni = 0; ni < 4; ni++) {
            int col = n0 + ni * 8 + lc * 2;
            gout[(size_t)r0 * NG + col]           = acc[mi][ni][0];
            gout[(size_t)r0 * NG + col + 1]       = acc[mi][ni][1];
            gout[(size_t)(r0 + 8) * NG + col]     = acc[mi][ni][2];
            gout[(size_t)(r0 + 8) * NG + col + 1] = acc[mi][ni][3];
        }
    }
}

// ---------------------------------------------------------------------------
// Pointwise step: float4 unit-major gate reads + rank-2 x contribution +
// prefetched tail scalars. grid = B_, 1024 threads.
// ---------------------------------------------------------------------------
__global__ void __launch_bounds__(1024, 1)
step_pointwise(const float* __restrict__ Wab, const float* __restrict__ Wxb,
               const float* __restrict__ Amat, const float* __restrict__ tau,
               const float* __restrict__ rnn_input,
               float* __restrict__ out, int s) {
    const int b = blockIdx.x;
    const int tid = threadIdx.x;
    const int lane = tid & 31;
    const int wid = tid >> 5;

    __shared__ float sPre[12];
    if (tid < 9) {
        float v;
        if (tid == 0)      v = tau[b * S_ + s];
        else if (tid < 5)  v = Amat[tid - 1];
        else if (tid < 7)  v = Wab[tid - 5];
        else               v = Wxb[tid - 7];
        sPre[tid] = v;
    }

    const float x0 = g_xstate[b * 2 + 0];
    const float x1 = g_xstate[b * 2 + 1];

    const float4* gb0 = (const float4*)(g_gates[0] + (size_t)b * NG);
    const float4* gb1 = (const float4*)(g_gates[1] + (size_t)b * NG);
    float* outz = out + ((size_t)b * S_ + s) * ZW;

    const int n = tid;  // unit index 0..1023
    float4 p0 = gb0[n];
    float4 p1 = gb1[n];
    float4 bi = g_bias4[n];
    float4 xa = g_wx2a[n];
    float4 xb = g_wx2b[n];
    float i_ = p0.x + p1.x + bi.x + x0 * xa.x + x1 * xb.x;
    float f_ = p0.y + p1.y + bi.y + x0 * xa.y + x1 * xb.y;
    float g_ = p0.z + p1.z + bi.z + x0 * xa.z + x1 * xb.z;
    float o_ = p0.w + p1.w + bi.w + x0 * xa.w + x1 * xb.w;
    float c  = g_cstate[b * H_ + n];
    float cn = sigf(f_) * c + sigf(i_) * tanhfast(g_);
    float hn = sigf(o_) * tanhfast(cn);
    g_cstate[b * H_ + n] = cn;
    store_x_hilo(b, IN_ + n, hn);
    outz[SD_ + n] = hn;

    float4 ww = g_wawx4[n];
    float wa0 = ww.x * hn;
    float wa1 = ww.y * hn;
    float wx0 = ww.z * hn;
    float wx1 = ww.w * hn;

    __shared__ float red[32][4];
    unsigned mask = 0xffffffffu;
#pragma unroll
    for (int off = 16; off > 0; off >>= 1) {
        wa0 += __shfl_down_sync(mask, wa0, off);
        wa1 += __shfl_down_sync(mask, wa1, off);
        wx0 += __shfl_down_sync(mask, wx0, off);
        wx1 += __shfl_down_sync(mask, wx1, off);
    }
    if (lane == 0) {
        red[wid][0] = wa0; red[wid][1] = wa1;
        red[wid][2] = wx0; red[wid][3] = wx1;
    }
    __syncthreads();

    if (wid == 0) {
        float s0 = red[lane][0], s1 = red[lane][1];
        float s2 = red[lane][2], s3 = red[lane][3];
#pragma unroll
        for (int off = 16; off > 0; off >>= 1) {
            s0 += __shfl_down_sync(mask, s0, off);
            s1 += __shfl_down_sync(mask, s1, off);
            s2 += __shfl_down_sync(mask, s2, off);
            s3 += __shfl_down_sync(mask, s3, off);
        }
        if (lane == 0) {
            float t   = sPre[0];
            float xm0 = x0 + t * (sPre[1] * x0 + sPre[2] * x1);
            float xm1 = x1 + t * (sPre[3] * x0 + sPre[4] * x1);
            float a0  = sigf(s0 + sPre[5]);
            float a1  = sigf(s1 + sPre[6]);
            float xt0 = s2 + sPre[7];
            float xt1 = s3 + sPre[8];
            float xn0 = a0 * xm0 + (1.0f - a0) * xt0;
            float xn1 = a1 * xm1 + (1.0f - a1) * xt1;
            g_xstate[b * 2 + 0] = xn0;
            g_xstate[b * 2 + 1] = xn1;
            outz[0] = xn0;
            outz[1] = xn1;
            float* cf = out + OUT_COEF + ((size_t)b * S_ + s) * SD_;
            cf[0] = a0;
            cf[1] = a1;
        }
    }

    if (s + 1 < S_ && tid >= 128 && tid < 128 + IN_) {
        int u = tid - 128;
        store_x_hilo(b, u, rnn_input[((size_t)b * S_ + (s + 1)) * IN_ + u]);
    }
}

// ---------------------------------------------------------------------------
// Final: z_f = outputs[:, -1, :], c_z_f = [c0[:, :2], c_final]
// ---------------------------------------------------------------------------
__global__ void final_out(const float* __restrict__ c0, float* __restrict__ out) {
    int b = blockIdx.x;
    float* zf  = out + OUT_ZF  + (size_t)b * ZW;
    float* czf = out + OUT_CZF + (size_t)b * ZW;
    const float* last = out + ((size_t)b * S_ + (S_ - 1)) * ZW;
    for (int k = threadIdx.x; k < ZW; k += 256) {
        zf[k] = last[k];
        czf[k] = (k < SD_) ? c0[b * ZW + k] : g_cstate[b * H_ + (k - SD_)];
    }
}

// ---------------------------------------------------------------------------
extern "C" void kernel_launch(void* const* d_in, const int* in_sizes, int n_in,
                              void* d_out, int out_size) {
    const float* rnn_input = (const float*)d_in[0];
    const float* z0        = (const float*)d_in[1];
    const float* c0        = (const float*)d_in[2];
    const float* tau       = (const float*)d_in[3];
    const float* A         = (const float*)d_in[4];
    const float* WU_w      = (const float*)d_in[5];
    const float* WU_b      = (const float*)d_in[6];
    const float* Wa_w      = (const float*)d_in[7];
    const float* Wa_b      = (const float*)d_in[8];
    const float* Wx_w      = (const float*)d_in[9];
    const float* Wx_b      = (const float*)d_in[10];
    float* out = (float*)d_out;

    cudaFuncSetAttribute(gates_hmma, cudaFuncAttributeMaxDynamicSharedMemorySize, SMEM_DYN);

    prep_w<<<dim3(64, NKB), 256>>>(WU_w);
    prep_small<<<4, 256>>>(WU_w, WU_b, Wa_w, Wx_w);
    init_pack<<<B_, 128>>>(z0, c0, rnn_input);
    for (int s = 0; s < S_; s++) {
        gates_hmma<<<dim3(64, 2), 256, SMEM_DYN>>>();
        step_pointwise<<<B_, 1024>>>(Wa_b, Wx_b, A, tau, rnn_input, out, s);
    }
    final_out<<<B_, 256>>>(c0, out);
}